// round 13
// baseline (speedup 1.0000x reference)
#include <cuda_runtime.h>
#include <cuda_bf16.h>
#include <math.h>
#include <stdint.h>

// Problem constants
#define BB 4
#define LL 4096
#define DD 1024
#define MM (BB*LL)        // 16384 tokens
#define FF 513            // rfft bins for D=1024
#define NCHUNK 64
#define CHTOK (LL/NCHUNK) // 64 tokens per chunk
#define NBLK_SCAN (BB*5*NCHUNK)   // 1280

// ---------------- scratch (static device globals; no runtime alloc) ----------
__device__ float  g_kv[(size_t)MM*2048];   // keys cols 0..1023, vals 1024..2047
__device__ float2 g_kf[(size_t)MM*FF];
__device__ float2 g_bf[(size_t)MM*FF];
__device__ float2 g_tw[1024];              // exp(-2*pi*i*k/1024)

__device__ float2 g_agg[(size_t)NBLK_SCAN*128];
__device__ float2 g_pre[(size_t)NBLK_SCAN*128];
__device__ int    g_flag[NBLK_SCAN];

__device__ __nv_bfloat16 g_xhi[MM*DD];
__device__ __nv_bfloat16 g_xlo[MM*DD];
__device__ __nv_bfloat16 g_rhi[MM*DD];
__device__ __nv_bfloat16 g_rlo[MM*DD];
__device__ __nv_bfloat16 g_wkvhi[2*DD*DD]; // [Wk;Wv] stacked, 2048 x 1024
__device__ __nv_bfloat16 g_wkvlo[2*DD*DD];
__device__ __nv_bfloat16 g_wohi[DD*DD];
__device__ __nv_bfloat16 g_wolo[DD*DD];
__device__ float g_bkv[2048];

// ---------------- helpers ----------------------------------------------------
__device__ __forceinline__ float2 cmul(float2 a, float2 b) {
    return make_float2(a.x*b.x - a.y*b.y, a.x*b.y + a.y*b.x);
}

// merged setup: twiddles + bias concat + flag reset (grid 2 x 1024)
__global__ void setup_kernel(const float* __restrict__ bk, const float* __restrict__ bv) {
    int i = blockIdx.x * 1024 + threadIdx.x;   // 0..2047
    g_bkv[i] = (i < 1024) ? bk[i] : bv[i - 1024];
    if (blockIdx.x == 0) {
        int k = threadIdx.x;
        double ang = -2.0 * 3.14159265358979323846 * (double)k / 1024.0;
        g_tw[k] = make_float2((float)cos(ang), (float)sin(ang));
    }
    if (i < NBLK_SCAN) g_flag[i] = 0;
}

// ---------------- fp32 -> bf16 hi/lo split ------------------------------------
__device__ __forceinline__ void split4(const float* __restrict__ in,
    __nv_bfloat16* __restrict__ hi, __nv_bfloat16* __restrict__ lo, int i)
{
    float4 v = reinterpret_cast<const float4*>(in)[i];
    __nv_bfloat16 h0 = __float2bfloat16(v.x);
    __nv_bfloat16 h1 = __float2bfloat16(v.y);
    __nv_bfloat16 h2 = __float2bfloat16(v.z);
    __nv_bfloat16 h3 = __float2bfloat16(v.w);
    __nv_bfloat16 l0 = __float2bfloat16(v.x - __bfloat162float(h0));
    __nv_bfloat16 l1 = __float2bfloat16(v.y - __bfloat162float(h1));
    __nv_bfloat16 l2 = __float2bfloat16(v.z - __bfloat162float(h2));
    __nv_bfloat16 l3 = __float2bfloat16(v.w - __bfloat162float(h3));
    __nv_bfloat162* hp = reinterpret_cast<__nv_bfloat162*>(hi) + 2*(size_t)i;
    __nv_bfloat162* lp = reinterpret_cast<__nv_bfloat162*>(lo) + 2*(size_t)i;
    hp[0] = __halves2bfloat162(h0, h1);
    hp[1] = __halves2bfloat162(h2, h3);
    lp[0] = __halves2bfloat162(l0, l1);
    lp[1] = __halves2bfloat162(l2, l3);
}

__global__ __launch_bounds__(256) void split_conv(const float* __restrict__ in,
    __nv_bfloat16* __restrict__ hi, __nv_bfloat16* __restrict__ lo, int n4)
{
    int i = blockIdx.x * 256 + threadIdx.x;
    if (i >= n4) return;
    split4(in, hi, lo, i);
}

// fused weight split: Wk, Wv -> wkv (stacked), Wo -> wo. 3072 blocks.
__global__ __launch_bounds__(256) void split_weights(
    const float* __restrict__ Wk, const float* __restrict__ Wv, const float* __restrict__ Wo)
{
    int nw4 = DD * DD / 4;           // 262144
    int gi = blockIdx.x * 256 + threadIdx.x;
    if (gi < nw4) {
        split4(Wk, g_wkvhi, g_wkvlo, gi);
    } else if (gi < 2 * nw4) {
        split4(Wv, g_wkvhi + (size_t)DD*DD, g_wkvlo + (size_t)DD*DD, gi - nw4);
    } else {
        split4(Wo, g_wohi, g_wolo, gi - 2 * nw4);
    }
}

// ---------------- mma.sync GEMM (portable PTX) --------------------------------
#define BN 128
#define BK 64
#define NSTG 3
#define NIT 48                          // 3 segments * 16 iters of K=64

__device__ __forceinline__ uint32_t s2u(const void* p) {
    uint32_t a;
    asm("{ .reg .u64 t; cvta.to.shared.u64 t, %1; cvt.u32.u64 %0, t; }" : "=r"(a) : "l"(p));
    return a;
}
// BK=64: each row is exactly 128B = one SW128 line. kc = 16B chunk (0..7).
__device__ __forceinline__ uint32_t tile_off(int row, int kc) {
    uint32_t off = (uint32_t)row * 128u + (uint32_t)(kc * 16);
    return off ^ ((off >> 3) & 0x70);
}
__device__ __forceinline__ void cp16(uint32_t dst, const void* src) {
    asm volatile("cp.async.cg.shared.global [%0], [%1], 16;" :: "r"(dst), "l"(src));
}
__device__ __forceinline__ void cp_commit() {
    asm volatile("cp.async.commit_group;" ::: "memory");
}
__device__ __forceinline__ void cp_wait(int n) {
    if (n >= 1) asm volatile("cp.async.wait_group 1;" ::: "memory");
    else        asm volatile("cp.async.wait_group 0;" ::: "memory");
}
__device__ __forceinline__ void ldm4(uint32_t* r, uint32_t addr) {
    asm volatile("ldmatrix.sync.aligned.m8n8.x4.shared.b16 {%0,%1,%2,%3}, [%4];"
                 : "=r"(r[0]), "=r"(r[1]), "=r"(r[2]), "=r"(r[3]) : "r"(addr));
}
__device__ __forceinline__ void mma16816(float* c, const uint32_t* a, uint32_t b0, uint32_t b1) {
    asm volatile(
        "mma.sync.aligned.m16n8k16.row.col.f32.bf16.bf16.f32 "
        "{%0,%1,%2,%3}, {%4,%5,%6,%7}, {%8,%9}, {%0,%1,%2,%3};"
        : "+f"(c[0]), "+f"(c[1]), "+f"(c[2]), "+f"(c[3])
        : "r"(a[0]), "r"(a[1]), "r"(a[2]), "r"(a[3]), "r"(b0), "r"(b1));
}

// Templated on TBM (64 or 128). 8 warps:
//  TBM=128: 4Mx2N warps, warp tile 32x64 (NT=8)
//  TBM=64 : 2Mx4N warps, warp tile 32x32 (NT=4)
template<int TBM>
__global__ __launch_bounds__(256) void gemm_mma(
    const __nv_bfloat16* __restrict__ Ahi, const __nv_bfloat16* __restrict__ Alo,
    const __nv_bfloat16* __restrict__ Bhi, const __nv_bfloat16* __restrict__ Blo,
    const float* __restrict__ bias, const float* __restrict__ res,
    float* __restrict__ out, int ldout)
{
    constexpr int NT = (TBM == 128) ? 8 : 4;      // N tiles of 8 per warp
    constexpr int NP = NT / 2;                    // B ldmatrix count
    constexpr int STG = (TBM*BK + BN*BK) * 2;     // stage bytes
    constexpr int ALOAD = (TBM*BK/8) / 256;       // 16B chunks per thread for A

    extern __shared__ char smem[];
    uint32_t sb = s2u(smem);
    int tid = threadIdx.x;
    int wid = tid >> 5, lane = tid & 31;
    int bm = blockIdx.y * TBM, bn = blockIdx.x * BN;
    int wm, wn;
    if (TBM == 128) { wm = (wid & 3) * 32; wn = (wid >> 2) * 64; }
    else            { wm = (wid & 1) * 32; wn = (wid >> 1) * 32; }

    const __nv_bfloat16* Asrc[3] = {Ahi, Ahi, Alo};
    const __nv_bfloat16* Bsrc[3] = {Bhi, Blo, Bhi};

    uint32_t offA[2][4], offB[NP][4];
#pragma unroll
    for (int mt = 0; mt < 2; mt++)
#pragma unroll
        for (int ks = 0; ks < 4; ks++) {
            int row = wm + mt*16 + (lane & 7) + ((lane >> 3) & 1) * 8;
            int kc  = ks*2 + (lane >> 4);
            offA[mt][ks] = tile_off(row, kc);
        }
#pragma unroll
    for (int p = 0; p < NP; p++)
#pragma unroll
        for (int ks = 0; ks < 4; ks++) {
            int row = wn + p*16 + (lane & 7) + (lane >> 4) * 8;
            int kc  = ks*2 + ((lane >> 3) & 1);
            offB[p][ks] = tile_off(row, kc);
        }

    float acc[2][NT][4];
#pragma unroll
    for (int mt = 0; mt < 2; mt++)
#pragma unroll
        for (int nt = 0; nt < NT; nt++)
#pragma unroll
            for (int q = 0; q < 4; q++) acc[mt][nt][q] = 0.0f;

    auto load_stage = [&](int slot, int iter) {
        int seg = iter >> 4;
        int k0  = (iter & 15) * BK;
        const __nv_bfloat16* A = Asrc[seg];
        const __nv_bfloat16* B = Bsrc[seg];
        uint32_t abase = sb + slot * STG;
        uint32_t bbase = abase + TBM * BK * 2;
#pragma unroll
        for (int j = 0; j < ALOAD; j++) {
            int idx = tid + j * 256;
            int row = idx >> 3, c = idx & 7;
            cp16(abase + tile_off(row, c), A + (size_t)(bm + row) * DD + k0 + c * 8);
        }
#pragma unroll
        for (int j = 0; j < 4; j++) {
            int idx = tid + j * 256;
            int row = idx >> 3, c = idx & 7;
            cp16(bbase + tile_off(row, c), B + (size_t)(bn + row) * DD + k0 + c * 8);
        }
        cp_commit();
    };

#pragma unroll
    for (int s = 0; s < NSTG - 1; s++) load_stage(s, s);

    for (int i = 0; i < NIT; i++) {
        int slot = i % NSTG;
        int pend = NIT - 1 - i; if (pend > NSTG - 2) pend = NSTG - 2;
        cp_wait(pend);
        __syncthreads();

        uint32_t abase = sb + slot * STG;
        uint32_t bbase = abase + TBM * BK * 2;
#pragma unroll
        for (int ks = 0; ks < 4; ks++) {
            uint32_t a[2][4], b[NP][4];
#pragma unroll
            for (int mt = 0; mt < 2; mt++) ldm4(a[mt], abase + offA[mt][ks]);
#pragma unroll
            for (int p = 0; p < NP; p++)   ldm4(b[p], bbase + offB[p][ks]);
#pragma unroll
            for (int mt = 0; mt < 2; mt++)
#pragma unroll
                for (int nt = 0; nt < NT; nt++)
                    mma16816(acc[mt][nt], a[mt], b[nt >> 1][(nt & 1) * 2], b[nt >> 1][(nt & 1) * 2 + 1]);
        }

        if (i + NSTG - 1 < NIT)
            load_stage((i + NSTG - 1) % NSTG, i + NSTG - 1);
    }

    int qr = lane >> 2, qc = (lane & 3) * 2;
#pragma unroll
    for (int mt = 0; mt < 2; mt++) {
#pragma unroll
        for (int nt = 0; nt < NT; nt++) {
            int col = bn + wn + nt * 8 + qc;
            float b0 = bias[col], b1 = bias[col + 1];
            int r0 = bm + wm + mt * 16 + qr;
            size_t g0 = (size_t)r0 * ldout + col;
            size_t g1 = g0 + (size_t)8 * ldout;
            float2 v0 = make_float2(acc[mt][nt][0] + b0, acc[mt][nt][1] + b1);
            float2 v1 = make_float2(acc[mt][nt][2] + b0, acc[mt][nt][3] + b1);
            if (res) {
                float2 x0 = *reinterpret_cast<const float2*>(res + g0);
                float2 x1 = *reinterpret_cast<const float2*>(res + g1);
                v0.x += x0.x; v0.y += x0.y;
                v1.x += x1.x; v1.y += x1.y;
            }
            *reinterpret_cast<float2*>(out + g0) = v0;
            *reinterpret_cast<float2*>(out + g1) = v1;
        }
    }
}

#define GEMM_SMEM_128 (NSTG*(128*BK + BN*BK)*2)   // 98304
#define GEMM_SMEM_64  (NSTG*(64*BK + BN*BK)*2)    // 73728

// ---------------- forward: norm keys, radix-4 FFT(k+iv), Kf & Kf*Vf ----------
// 2 tokens per 512-thread block; 256 threads per token.  (R10 proven config)
__global__ __launch_bounds__(512) void fwd_kernel() {
    __shared__ float2 sA[2][1024];
    __shared__ float2 sB[2][1024];
    __shared__ float red[16];
    int tid = threadIdx.x;
    int slot = tid >> 8;          // 0..1
    int ltid = tid & 255;
    int t = blockIdx.x * 2 + slot;

    const float* krow = g_kv + (size_t)t * 2048;
    const float* vrow = krow + 1024;
    float kx[4], vx[4];
#pragma unroll
    for (int m = 0; m < 4; m++) {
        kx[m] = krow[ltid + 256*m];
        vx[m] = vrow[ltid + 256*m];
    }

    float ss = kx[0]*kx[0] + kx[1]*kx[1] + kx[2]*kx[2] + kx[3]*kx[3];
#pragma unroll
    for (int o = 16; o; o >>= 1) ss += __shfl_xor_sync(0xffffffffu, ss, o);
    if ((tid & 31) == 0) red[tid >> 5] = ss;
    __syncthreads();
    float tot = 0.f;
#pragma unroll
    for (int w = 0; w < 8; w++) tot += red[slot*8 + w];
    float scale = 1.0f / fmaxf(sqrtf(tot), 1e-12f);

#pragma unroll
    for (int m = 0; m < 4; m++)
        sA[slot][ltid + 256*m] = make_float2(kx[m]*scale, vx[m]);
    __syncthreads();

    // 5 radix-4 Stockham stages, N=1024
    float2* src = sA[slot];
    float2* dst = sB[slot];
#pragma unroll
    for (int s = 0; s < 5; s++) {
        int Ns = 1 << (2*s);
        int j = ltid;
        int k = j & (Ns - 1);
        int twi = k << (8 - 2*s);          // 256*k/Ns
        float2 w1 = g_tw[twi];
        float2 w2 = g_tw[2*twi];
        float2 w3 = g_tw[3*twi];
        float2 a = src[j];
        float2 b = cmul(src[j + 256], w1);
        float2 c = cmul(src[j + 512], w2);
        float2 d = cmul(src[j + 768], w3);
        float2 t0 = make_float2(a.x + c.x, a.y + c.y);
        float2 t1 = make_float2(a.x - c.x, a.y - c.y);
        float2 t2 = make_float2(b.x + d.x, b.y + d.y);
        float2 t3 = make_float2(b.y - d.y, d.x - b.x);   // -i*(b-d)
        int idx = ((j >> (2*s)) << (2*s + 2)) + k;
        dst[idx]        = make_float2(t0.x + t2.x, t0.y + t2.y);
        dst[idx + Ns]   = make_float2(t1.x + t3.x, t1.y + t3.y);
        dst[idx + 2*Ns] = make_float2(t0.x - t2.x, t0.y - t2.y);
        dst[idx + 3*Ns] = make_float2(t1.x - t3.x, t1.y - t3.y);
        __syncthreads();
        float2* tmp = src; src = dst; dst = tmp;
    }
    // result in src

#pragma unroll
    for (int e = 0; e < 3; e++) {
        int f;
        if (e < 2) f = ltid + 256*e;
        else { if (ltid != 0) break; f = 512; }
        float2 Zf = src[f];
        float2 Zn = src[(1024 - f) & 1023];
        float2 Kf = make_float2(0.5f*(Zf.x + Zn.x), 0.5f*(Zf.y - Zn.y));
        float2 Vf = make_float2(0.5f*(Zf.y + Zn.y), 0.5f*(Zn.x - Zf.x));
        size_t idx = (size_t)t * FF + f;
        g_kf[idx] = Kf;
        g_bf[idx] = cmul(Kf, Vf);
    }
}

// ---------------- single-pass decoupled-lookback scan + unbind ----------------
__global__ __launch_bounds__(128) void scan_fused() {
    __shared__ int sflag;
    int tid = threadIdx.x;
    int bidx = blockIdx.x;
    int chain = bidx >> 6;          // 0..19  = b*5 + fg
    int c = bidx & 63;
    int b = chain / 5;
    int fg = chain % 5;
    int f = fg * 128 + tid;
    bool active = (f < FF);
    int tok0 = b * LL + c * CHTOK;

    // phase 1: chunk aggregate
    float2 sum = make_float2(0.f, 0.f);
    if (active) {
#pragma unroll 4
        for (int tt = 0; tt < CHTOK; tt++) {
            float2 v = g_bf[(size_t)(tok0 + tt) * FF + f];
            sum.x += v.x; sum.y += v.y;
        }
    }

    if (c == 0) {
        if (active) g_pre[(size_t)bidx * 128 + tid] = sum;
        __threadfence();
        __syncthreads();
        if (tid == 0) atomicExch(&g_flag[bidx], 2);
    } else {
        if (active) g_agg[(size_t)bidx * 128 + tid] = sum;
        __threadfence();
        __syncthreads();
        if (tid == 0) atomicExch(&g_flag[bidx], 1);
    }

    // lookback for exclusive prefix
    float2 run = make_float2(0.f, 0.f);
    if (c > 0) {
        int look = bidx - 1;
        while (true) {
            if (tid == 0) {
                int fl;
                do { fl = atomicAdd(&g_flag[look], 0); } while (fl == 0);
                sflag = fl;
            }
            __syncthreads();
            int fl = sflag;
            __threadfence();
            if (active) {
                float2 p = (fl == 2) ? g_pre[(size_t)look * 128 + tid]
                                     : g_agg[(size_t)look * 128 + tid];
                run.x += p.x; run.y += p.y;
            }
            __syncthreads();
            if (fl == 2) break;
            look--;
        }
        if (active)
            g_pre[(size_t)bidx * 128 + tid] = make_float2(run.x + sum.x, run.y + sum.y);
        __threadfence();
        __syncthreads();
        if (tid == 0) atomicExch(&g_flag[bidx], 2);
    }

    // phase 2: cumsum + unbind rf = Mf * conj(Kf)  (chunk re-read mostly L2-hit)
    if (active) {
        float2 acc = run;
        for (int tt = 0; tt < CHTOK; tt++) {
            size_t idx = (size_t)(tok0 + tt) * FF + f;
            float2 v = g_bf[idx];
            acc.x += v.x; acc.y += v.y;
            float2 kf = g_kf[idx];
            g_bf[idx] = make_float2(acc.x*kf.x + acc.y*kf.y, acc.y*kf.x - acc.x*kf.y);
        }
    }
}

// ---------------- inverse: 512-pt complex IFFT + LN + bf16 hi/lo split -------
// 4 tokens per 512-thread block; 128 threads per token.
__global__ __launch_bounds__(512) void inv_kernel(const float* __restrict__ ln_g,
                                                  const float* __restrict__ ln_b) {
    __shared__ float2 sA[4][512];
    __shared__ float2 sB[4][512];
    __shared__ float2 rfny[4];
    __shared__ float red1[16];
    __shared__ float red2[16];
    int tid = threadIdx.x;
    int slot = tid >> 7;           // 0..3
    int ltid = tid & 127;
    int t = blockIdx.x * 4 + slot;
    int l = t % LL;

    const float2* rf = g_bf + (size_t)t * FF;
#pragma unroll
    for (int m = 0; m < 4; m++)
        sA[slot][ltid + 128*m] = rf[ltid + 128*m];
    if (ltid == 0) rfny[slot] = rf[512];
    __syncthreads();

    // Z[k] = 0.5*(X[k]+conj(X[512-k])) + 0.5*i*e^{+i*2pi*k/1024}*(X[k]-conj(X[512-k]))
#pragma unroll
    for (int m = 0; m < 4; m++) {
        int k = ltid + 128*m;
        float2 Xk = sA[slot][k];
        float2 Xm = (k == 0) ? rfny[slot] : sA[slot][512 - k];
        float2 sum = make_float2(Xk.x + Xm.x, Xk.y - Xm.y);
        float2 dif = make_float2(Xk.x - Xm.x, Xk.y + Xm.y);
        float2 wc = make_float2(g_tw[k].x, -g_tw[k].y);
        float2 t2 = cmul(wc, dif);
        sB[slot][k] = make_float2(0.5f*(sum.x - t2.y), 0.5f*(sum.y + t2.x));
    }
    __syncthreads();

    // inverse 512-pt FFT: 4 radix-4 stages + 1 radix-2 stage (conjugated twiddles)
    float2* src = sB[slot];
    float2* dst = sA[slot];
#pragma unroll
    for (int s = 0; s < 4; s++) {
        int Ns = 1 << (2*s);
        int j = ltid;
        int k = j & (Ns - 1);
        int twi = k << (8 - 2*s);
        float2 w1 = make_float2(g_tw[twi].x,   -g_tw[twi].y);
        float2 w2 = make_float2(g_tw[2*twi].x, -g_tw[2*twi].y);
        float2 w3 = make_float2(g_tw[3*twi].x, -g_tw[3*twi].y);
        float2 a = src[j];
        float2 b = cmul(src[j + 128], w1);
        float2 c = cmul(src[j + 256], w2);
        float2 d = cmul(src[j + 384], w3);
        float2 t0 = make_float2(a.x + c.x, a.y + c.y);
        float2 t1 = make_float2(a.x - c.x, a.y - c.y);
        float2 t2 = make_float2(b.x + d.x, b.y + d.y);
        float2 t3 = make_float2(d.y - b.y, b.x - d.x);   // +i*(b-d)
        int idx = ((j >> (2*s)) << (2*s + 2)) + k;
        dst[idx]        = make_float2(t0.x + t2.x, t0.y + t2.y);
        dst[idx + Ns]   = make_float2(t1.x + t3.x, t1.y + t3.y);
        dst[idx + 2*Ns] = make_float2(t0.x - t2.x, t0.y - t2.y);
        dst[idx + 3*Ns] = make_float2(t1.x - t3.x, t1.y - t3.y);
        __syncthreads();
        float2* tmp = src; src = dst; dst = tmp;
    }
    // radix-2 final stage
#pragma unroll
    for (int q = 0; q < 2; q++) {
        int j = ltid + 128*q;
        float2 w = make_float2(g_tw[2*j].x, -g_tw[2*j].y);
        float2 v0 = src[j];
        float2 v1 = src[j + 256];
        float2 tt = cmul(v1, w);
        dst[j]       = make_float2(v0.x + tt.x, v0.y + tt.y);
        dst[j + 256] = make_float2(v0.x - tt.x, v0.y - tt.y);
    }
    __syncthreads();
    float2* Z = dst;

    float s = (1.0f / 512.0f) * rsqrtf((float)(l + 1));
    float2 z0 = Z[2*ltid];
    float2 z1 = Z[2*ltid + 1];
    float2 z2 = Z[2*ltid + 256];
    float2 z3 = Z[2*ltid + 257];
    float xa0 = z0.x * s, xa1 = z0.y * s, xa2 = z1.x * s, xa3 = z1.y * s;
    float xb0 = z2.x * s, xb1 = z2.y * s, xb2 = z3.x * s, xb3 = z3.y * s;

    float sum = xa0 + xa1 + xa2 + xa3 + xb0 + xb1 + xb2 + xb3;
    float sq  = xa0*xa0 + xa1*xa1 + xa2*xa2 + xa3*xa3
              + xb0*xb0 + xb1*xb1 + xb2*xb2 + xb3*xb3;
#pragma unroll
    for (int o = 16; o; o >>= 1) {
        sum += __shfl_xor_sync(0xffffffffu, sum, o);
        sq  += __shfl_xor_sync(0xffffffffu, sq, o);
    }
    if ((tid & 31) == 0) { red1[tid >> 5] = sum; red2[tid >> 5] = sq; }
    __syncthreads();
    float tsum = 0.f, tsq = 0.f;
#pragma unroll
    for (int w = 0; w < 4; w++) { tsum += red1[slot*4 + w]; tsq += red2[slot*4 + w]; }
    float mu  = tsum * (1.0f / 1024.0f);
    float var = tsq * (1.0f / 1024.0f) - mu * mu;
    float inv = rsqrtf(var + 1e-5f);

    int colA = 4 * ltid;
    int colB = 512 + 4 * ltid;
    float4 gA = *reinterpret_cast<const float4*>(ln_g + colA);
    float4 bA = *reinterpret_cast<const float4*>(ln_b + colA);
    float4 gB = *reinterpret_cast<const float4*>(ln_g + colB);
    float4 bB = *reinterpret_cast<const float4*>(ln_b + colB);
    float rA[4], rB[4];
    rA[0] = (xa0 - mu) * inv * gA.x + bA.x;
    rA[1] = (xa1 - mu) * inv * gA.y + bA.y;
    rA[2] = (xa2 - mu) * inv * gA.z + bA.z;
    rA[3] = (xa3 - mu) * inv * gA.w + bA.w;
    rB[0] = (xb0 - mu) * inv * gB.x + bB.x;
    rB[1] = (xb1 - mu) * inv * gB.y + bB.y;
    rB[2] = (xb2 - mu) * inv * gB.z + bB.z;
    rB[3] = (xb3 - mu) * inv * gB.w + bB.w;

    size_t rowoff = (size_t)t * DD;
    __nv_bfloat16 hA[4], lA[4], hB[4], lB[4];
#pragma unroll
    for (int q = 0; q < 4; q++) {
        hA[q] = __float2bfloat16(rA[q]);
        lA[q] = __float2bfloat16(rA[q] - __bfloat162float(hA[q]));
        hB[q] = __float2bfloat16(rB[q]);
        lB[q] = __float2bfloat16(rB[q] - __bfloat162float(hB[q]));
    }
    __nv_bfloat162* hpA = reinterpret_cast<__nv_bfloat162*>(g_rhi + rowoff + colA);
    __nv_bfloat162* lpA = reinterpret_cast<__nv_bfloat162*>(g_rlo + rowoff + colA);
    __nv_bfloat162* hpB = reinterpret_cast<__nv_bfloat162*>(g_rhi + rowoff + colB);
    __nv_bfloat162* lpB = reinterpret_cast<__nv_bfloat162*>(g_rlo + rowoff + colB);
    hpA[0] = __halves2bfloat162(hA[0], hA[1]); hpA[1] = __halves2bfloat162(hA[2], hA[3]);
    lpA[0] = __halves2bfloat162(lA[0], lA[1]); lpA[1] = __halves2bfloat162(lA[2], lA[3]);
    hpB[0] = __halves2bfloat162(hB[0], hB[1]); hpB[1] = __halves2bfloat162(hB[2], hB[3]);
    lpB[0] = __halves2bfloat162(lB[0], lB[1]); lpB[1] = __halves2bfloat162(lB[2], lB[3]);
}

// ---------------- launch ------------------------------------------------------
extern "C" void kernel_launch(void* const* d_in, const int* in_sizes, int n_in,
                              void* d_out, int out_size) {
    const float* x    = (const float*)d_in[0];
    const float* Wk   = (const float*)d_in[1];
    const float* bk   = (const float*)d_in[2];
    const float* Wv   = (const float*)d_in[3];
    const float* bv   = (const float*)d_in[4];
    const float* ln_g = (const float*)d_in[5];
    const float* ln_b = (const float*)d_in[6];
    const float* Wo   = (const float*)d_in[7];
    const float* bo   = (const float*)d_in[8];
    float* out = (float*)d_out;

    void *p_kv;
    void *p_xhi, *p_xlo, *p_rhi, *p_rlo;
    void *p_wkvhi, *p_wkvlo, *p_wohi, *p_wolo, *p_bkv;
    cudaGetSymbolAddress(&p_kv,   g_kv);
    cudaGetSymbolAddress(&p_xhi,  g_xhi);
    cudaGetSymbolAddress(&p_xlo,  g_xlo);
    cudaGetSymbolAddress(&p_rhi,  g_rhi);
    cudaGetSymbolAddress(&p_rlo,  g_rlo);
    cudaGetSymbolAddress(&p_wkvhi, g_wkvhi);
    cudaGetSymbolAddress(&p_wkvlo, g_wkvlo);
    cudaGetSymbolAddress(&p_wohi, g_wohi);
    cudaGetSymbolAddress(&p_wolo, g_wolo);
    cudaGetSymbolAddress(&p_bkv,  g_bkv);

    cudaFuncSetAttribute(gemm_mma<128>, cudaFuncAttributeMaxDynamicSharedMemorySize, GEMM_SMEM_128);
    cudaFuncSetAttribute(gemm_mma<64>,  cudaFuncAttributeMaxDynamicSharedMemorySize, GEMM_SMEM_64);

    setup_kernel<<<2, 1024>>>(bk, bv);

    int nx4 = MM * DD / 4;
    int nw4 = DD * DD / 4;
    split_conv<<<(nx4 + 255)/256, 256>>>(x, (__nv_bfloat16*)p_xhi, (__nv_bfloat16*)p_xlo, nx4);
    split_weights<<<(3*nw4 + 255)/256, 256>>>(Wk, Wv, Wo);

    // fused K+V projection: N = 2048, BM=128
    dim3 kvgrid(2048 / BN, MM / 128);   // (16, 128)
    gemm_mma<128><<<kvgrid, 256, GEMM_SMEM_128>>>((__nv_bfloat16*)p_xhi, (__nv_bfloat16*)p_xlo,
                                         (__nv_bfloat16*)p_wkvhi, (__nv_bfloat16*)p_wkvlo,
                                         (const float*)p_bkv, nullptr, (float*)p_kv, 2048);

    fwd_kernel<<<MM/2, 512>>>();

    scan_fused<<<NBLK_SCAN, 128>>>();

    inv_kernel<<<MM/4, 512>>>(ln_g, ln_b);

    // Wo GEMM with BM=64: 2048 tiles -> minimal wave-quantization tail
    dim3 ogrid(DD / BN, MM / 64);      // (8, 256)
    gemm_mma<64><<<ogrid, 256, GEMM_SMEM_64>>>((__nv_bfloat16*)p_rhi, (__nv_bfloat16*)p_rlo,
                                        (__nv_bfloat16*)p_wohi, (__nv_bfloat16*)p_wolo,
                                        bo, x, out, DD);
}

// round 14
// speedup vs baseline: 1.0272x; 1.0272x over previous
#include <cuda_runtime.h>
#include <cuda_bf16.h>
#include <math.h>
#include <stdint.h>

// Problem constants
#define BB 4
#define LL 4096
#define DD 1024
#define MM (BB*LL)        // 16384 tokens
#define FF 513            // rfft bins for D=1024
#define NCHUNK 64
#define CHTOK (LL/NCHUNK) // 64 tokens per chunk
#define NBLK_SCAN (BB*5*NCHUNK)   // 1280

// ---------------- scratch (static device globals; no runtime alloc) ----------
__device__ float  g_kv[(size_t)MM*2048];   // keys cols 0..1023, vals 1024..2047
__device__ float2 g_kf[(size_t)MM*FF];
__device__ float2 g_bf[(size_t)MM*FF];
__device__ float2 g_tw[1024];              // exp(-2*pi*i*k/1024)

__device__ float2 g_agg[(size_t)NBLK_SCAN*128];
__device__ float2 g_pre[(size_t)NBLK_SCAN*128];
__device__ int    g_flag[NBLK_SCAN];

__device__ __nv_bfloat16 g_xhi[MM*DD];
__device__ __nv_bfloat16 g_xlo[MM*DD];
__device__ __nv_bfloat16 g_rhi[MM*DD];
__device__ __nv_bfloat16 g_rlo[MM*DD];
__device__ __nv_bfloat16 g_wkvhi[2*DD*DD]; // [Wk;Wv] stacked, 2048 x 1024
__device__ __nv_bfloat16 g_wkvlo[2*DD*DD];
__device__ __nv_bfloat16 g_wohi[DD*DD];
__device__ __nv_bfloat16 g_wolo[DD*DD];
__device__ float g_bkv[2048];

// ---------------- helpers ----------------------------------------------------
__device__ __forceinline__ float2 cmul(float2 a, float2 b) {
    return make_float2(a.x*b.x - a.y*b.y, a.x*b.y + a.y*b.x);
}

// merged setup: twiddles + bias concat + flag reset (grid 2 x 1024)
__global__ void setup_kernel(const float* __restrict__ bk, const float* __restrict__ bv) {
    int i = blockIdx.x * 1024 + threadIdx.x;   // 0..2047
    g_bkv[i] = (i < 1024) ? bk[i] : bv[i - 1024];
    if (blockIdx.x == 0) {
        int k = threadIdx.x;
        double ang = -2.0 * 3.14159265358979323846 * (double)k / 1024.0;
        g_tw[k] = make_float2((float)cos(ang), (float)sin(ang));
    }
    if (i < NBLK_SCAN) g_flag[i] = 0;
}

// ---------------- fp32 -> bf16 hi/lo split ------------------------------------
__device__ __forceinline__ void split4(const float* __restrict__ in,
    __nv_bfloat16* __restrict__ hi, __nv_bfloat16* __restrict__ lo, int i)
{
    float4 v = reinterpret_cast<const float4*>(in)[i];
    __nv_bfloat16 h0 = __float2bfloat16(v.x);
    __nv_bfloat16 h1 = __float2bfloat16(v.y);
    __nv_bfloat16 h2 = __float2bfloat16(v.z);
    __nv_bfloat16 h3 = __float2bfloat16(v.w);
    __nv_bfloat16 l0 = __float2bfloat16(v.x - __bfloat162float(h0));
    __nv_bfloat16 l1 = __float2bfloat16(v.y - __bfloat162float(h1));
    __nv_bfloat16 l2 = __float2bfloat16(v.z - __bfloat162float(h2));
    __nv_bfloat16 l3 = __float2bfloat16(v.w - __bfloat162float(h3));
    __nv_bfloat162* hp = reinterpret_cast<__nv_bfloat162*>(hi) + 2*(size_t)i;
    __nv_bfloat162* lp = reinterpret_cast<__nv_bfloat162*>(lo) + 2*(size_t)i;
    hp[0] = __halves2bfloat162(h0, h1);
    hp[1] = __halves2bfloat162(h2, h3);
    lp[0] = __halves2bfloat162(l0, l1);
    lp[1] = __halves2bfloat162(l2, l3);
}

__global__ __launch_bounds__(256) void split_conv(const float* __restrict__ in,
    __nv_bfloat16* __restrict__ hi, __nv_bfloat16* __restrict__ lo, int n4)
{
    int i = blockIdx.x * 256 + threadIdx.x;
    if (i >= n4) return;
    split4(in, hi, lo, i);
}

// fused weight split: Wk, Wv -> wkv (stacked), Wo -> wo. 3072 blocks.
__global__ __launch_bounds__(256) void split_weights(
    const float* __restrict__ Wk, const float* __restrict__ Wv, const float* __restrict__ Wo)
{
    int nw4 = DD * DD / 4;           // 262144
    int gi = blockIdx.x * 256 + threadIdx.x;
    if (gi < nw4) {
        split4(Wk, g_wkvhi, g_wkvlo, gi);
    } else if (gi < 2 * nw4) {
        split4(Wv, g_wkvhi + (size_t)DD*DD, g_wkvlo + (size_t)DD*DD, gi - nw4);
    } else {
        split4(Wo, g_wohi, g_wolo, gi - 2 * nw4);
    }
}

// ---------------- mma.sync GEMM (portable PTX) --------------------------------
// R12-proven: 128x128 CTA tile, 8 warps (4Mx2N), BK=64, 3 stages, 2 CTA/SM.
#define BM 128
#define BN 128
#define BK 64
#define NSTG 3
#define NIT 48                          // 3 segments * 16 iters of K=64
#define STG_BYTES ((BM*BK + BN*BK)*2)   // 32768
#define GEMM_SMEM (NSTG*STG_BYTES)      // 98304

__device__ __forceinline__ uint32_t s2u(const void* p) {
    uint32_t a;
    asm("{ .reg .u64 t; cvta.to.shared.u64 t, %1; cvt.u32.u64 %0, t; }" : "=r"(a) : "l"(p));
    return a;
}
// BK=64: each row is exactly 128B = one SW128 line. kc = 16B chunk (0..7).
__device__ __forceinline__ uint32_t tile_off(int row, int kc) {
    uint32_t off = (uint32_t)row * 128u + (uint32_t)(kc * 16);
    return off ^ ((off >> 3) & 0x70);
}
__device__ __forceinline__ void cp16(uint32_t dst, const void* src) {
    asm volatile("cp.async.cg.shared.global [%0], [%1], 16;" :: "r"(dst), "l"(src));
}
__device__ __forceinline__ void cp_commit() {
    asm volatile("cp.async.commit_group;" ::: "memory");
}
__device__ __forceinline__ void cp_wait(int n) {
    if (n >= 1) asm volatile("cp.async.wait_group 1;" ::: "memory");
    else        asm volatile("cp.async.wait_group 0;" ::: "memory");
}
__device__ __forceinline__ void ldm4(uint32_t* r, uint32_t addr) {
    asm volatile("ldmatrix.sync.aligned.m8n8.x4.shared.b16 {%0,%1,%2,%3}, [%4];"
                 : "=r"(r[0]), "=r"(r[1]), "=r"(r[2]), "=r"(r[3]) : "r"(addr));
}
__device__ __forceinline__ void mma16816(float* c, const uint32_t* a, uint32_t b0, uint32_t b1) {
    asm volatile(
        "mma.sync.aligned.m16n8k16.row.col.f32.bf16.bf16.f32 "
        "{%0,%1,%2,%3}, {%4,%5,%6,%7}, {%8,%9}, {%0,%1,%2,%3};"
        : "+f"(c[0]), "+f"(c[1]), "+f"(c[2]), "+f"(c[3])
        : "r"(a[0]), "r"(a[1]), "r"(a[2]), "r"(a[3]), "r"(b0), "r"(b1));
}

__global__ __launch_bounds__(256) void gemm_mma(
    const __nv_bfloat16* __restrict__ Ahi, const __nv_bfloat16* __restrict__ Alo,
    const __nv_bfloat16* __restrict__ Bhi, const __nv_bfloat16* __restrict__ Blo,
    const float* __restrict__ bias, const float* __restrict__ res,
    float* __restrict__ out, int ldout)
{
    extern __shared__ char smem[];
    uint32_t sb = s2u(smem);
    int tid = threadIdx.x;
    int wid = tid >> 5, lane = tid & 31;
    int bm = blockIdx.y * BM, bn = blockIdx.x * BN;
    int wm = (wid & 3) * 32;
    int wn = (wid >> 2) * 64;

    const __nv_bfloat16* Asrc[3] = {Ahi, Ahi, Alo};
    const __nv_bfloat16* Bsrc[3] = {Bhi, Blo, Bhi};

    uint32_t offA[2][4], offB[4][4];
#pragma unroll
    for (int mt = 0; mt < 2; mt++)
#pragma unroll
        for (int ks = 0; ks < 4; ks++) {
            int row = wm + mt*16 + (lane & 7) + ((lane >> 3) & 1) * 8;
            int kc  = ks*2 + (lane >> 4);
            offA[mt][ks] = tile_off(row, kc);
        }
#pragma unroll
    for (int p = 0; p < 4; p++)
#pragma unroll
        for (int ks = 0; ks < 4; ks++) {
            int row = wn + p*16 + (lane & 7) + (lane >> 4) * 8;
            int kc  = ks*2 + ((lane >> 3) & 1);
            offB[p][ks] = tile_off(row, kc);
        }

    float acc[2][8][4];
#pragma unroll
    for (int mt = 0; mt < 2; mt++)
#pragma unroll
        for (int nt = 0; nt < 8; nt++)
#pragma unroll
            for (int q = 0; q < 4; q++) acc[mt][nt][q] = 0.0f;

    auto load_stage = [&](int slot, int iter) {
        int seg = iter >> 4;
        int k0  = (iter & 15) * BK;
        const __nv_bfloat16* A = Asrc[seg];
        const __nv_bfloat16* B = Bsrc[seg];
        uint32_t abase = sb + slot * STG_BYTES;
        uint32_t bbase = abase + BM * BK * 2;
#pragma unroll
        for (int j = 0; j < 4; j++) {
            int idx = tid + j * 256;
            int row = idx >> 3, c = idx & 7;
            cp16(abase + tile_off(row, c), A + (size_t)(bm + row) * DD + k0 + c * 8);
        }
#pragma unroll
        for (int j = 0; j < 4; j++) {
            int idx = tid + j * 256;
            int row = idx >> 3, c = idx & 7;
            cp16(bbase + tile_off(row, c), B + (size_t)(bn + row) * DD + k0 + c * 8);
        }
        cp_commit();
    };

#pragma unroll
    for (int s = 0; s < NSTG - 1; s++) load_stage(s, s);

    for (int i = 0; i < NIT; i++) {
        int slot = i % NSTG;
        int pend = NIT - 1 - i; if (pend > NSTG - 2) pend = NSTG - 2;
        cp_wait(pend);
        __syncthreads();

        uint32_t abase = sb + slot * STG_BYTES;
        uint32_t bbase = abase + BM * BK * 2;
#pragma unroll
        for (int ks = 0; ks < 4; ks++) {
            uint32_t a[2][4], b[4][4];
#pragma unroll
            for (int mt = 0; mt < 2; mt++) ldm4(a[mt], abase + offA[mt][ks]);
#pragma unroll
            for (int p = 0; p < 4; p++)    ldm4(b[p], bbase + offB[p][ks]);
#pragma unroll
            for (int mt = 0; mt < 2; mt++)
#pragma unroll
                for (int nt = 0; nt < 8; nt++)
                    mma16816(acc[mt][nt], a[mt], b[nt >> 1][(nt & 1) * 2], b[nt >> 1][(nt & 1) * 2 + 1]);
        }

        if (i + NSTG - 1 < NIT)
            load_stage((i + NSTG - 1) % NSTG, i + NSTG - 1);
    }

    int qr = lane >> 2, qc = (lane & 3) * 2;
#pragma unroll
    for (int mt = 0; mt < 2; mt++) {
#pragma unroll
        for (int nt = 0; nt < 8; nt++) {
            int col = bn + wn + nt * 8 + qc;
            float b0 = bias[col], b1 = bias[col + 1];
            int r0 = bm + wm + mt * 16 + qr;
            size_t g0 = (size_t)r0 * ldout + col;
            size_t g1 = g0 + (size_t)8 * ldout;
            float2 v0 = make_float2(acc[mt][nt][0] + b0, acc[mt][nt][1] + b1);
            float2 v1 = make_float2(acc[mt][nt][2] + b0, acc[mt][nt][3] + b1);
            if (res) {
                float2 x0 = *reinterpret_cast<const float2*>(res + g0);
                float2 x1 = *reinterpret_cast<const float2*>(res + g1);
                v0.x += x0.x; v0.y += x0.y;
                v1.x += x1.x; v1.y += x1.y;
            }
            *reinterpret_cast<float2*>(out + g0) = v0;
            *reinterpret_cast<float2*>(out + g1) = v1;
        }
    }
}

// ---------------- forward: norm keys, radix-4 FFT(k+iv), Kf & Kf*Vf ----------
// 2 tokens per 512-thread block; 256 threads per token.  (R10 proven config)
__global__ __launch_bounds__(512) void fwd_kernel() {
    __shared__ float2 sA[2][1024];
    __shared__ float2 sB[2][1024];
    __shared__ float red[16];
    int tid = threadIdx.x;
    int slot = tid >> 8;          // 0..1
    int ltid = tid & 255;
    int t = blockIdx.x * 2 + slot;

    const float* krow = g_kv + (size_t)t * 2048;
    const float* vrow = krow + 1024;
    float kx[4], vx[4];
#pragma unroll
    for (int m = 0; m < 4; m++) {
        kx[m] = krow[ltid + 256*m];
        vx[m] = vrow[ltid + 256*m];
    }

    float ss = kx[0]*kx[0] + kx[1]*kx[1] + kx[2]*kx[2] + kx[3]*kx[3];
#pragma unroll
    for (int o = 16; o; o >>= 1) ss += __shfl_xor_sync(0xffffffffu, ss, o);
    if ((tid & 31) == 0) red[tid >> 5] = ss;
    __syncthreads();
    float tot = 0.f;
#pragma unroll
    for (int w = 0; w < 8; w++) tot += red[slot*8 + w];
    float scale = 1.0f / fmaxf(sqrtf(tot), 1e-12f);

#pragma unroll
    for (int m = 0; m < 4; m++)
        sA[slot][ltid + 256*m] = make_float2(kx[m]*scale, vx[m]);
    __syncthreads();

    // 5 radix-4 Stockham stages, N=1024
    float2* src = sA[slot];
    float2* dst = sB[slot];
#pragma unroll
    for (int s = 0; s < 5; s++) {
        int Ns = 1 << (2*s);
        int j = ltid;
        int k = j & (Ns - 1);
        int twi = k << (8 - 2*s);          // 256*k/Ns
        float2 w1 = g_tw[twi];
        float2 w2 = g_tw[2*twi];
        float2 w3 = g_tw[3*twi];
        float2 a = src[j];
        float2 b = cmul(src[j + 256], w1);
        float2 c = cmul(src[j + 512], w2);
        float2 d = cmul(src[j + 768], w3);
        float2 t0 = make_float2(a.x + c.x, a.y + c.y);
        float2 t1 = make_float2(a.x - c.x, a.y - c.y);
        float2 t2 = make_float2(b.x + d.x, b.y + d.y);
        float2 t3 = make_float2(b.y - d.y, d.x - b.x);   // -i*(b-d)
        int idx = ((j >> (2*s)) << (2*s + 2)) + k;
        dst[idx]        = make_float2(t0.x + t2.x, t0.y + t2.y);
        dst[idx + Ns]   = make_float2(t1.x + t3.x, t1.y + t3.y);
        dst[idx + 2*Ns] = make_float2(t0.x - t2.x, t0.y - t2.y);
        dst[idx + 3*Ns] = make_float2(t1.x - t3.x, t1.y - t3.y);
        __syncthreads();
        float2* tmp = src; src = dst; dst = tmp;
    }
    // result in src

#pragma unroll
    for (int e = 0; e < 3; e++) {
        int f;
        if (e < 2) f = ltid + 256*e;
        else { if (ltid != 0) break; f = 512; }
        float2 Zf = src[f];
        float2 Zn = src[(1024 - f) & 1023];
        float2 Kf = make_float2(0.5f*(Zf.x + Zn.x), 0.5f*(Zf.y - Zn.y));
        float2 Vf = make_float2(0.5f*(Zf.y + Zn.y), 0.5f*(Zn.x - Zf.x));
        size_t idx = (size_t)t * FF + f;
        g_kf[idx] = Kf;
        g_bf[idx] = cmul(Kf, Vf);
    }
}

// ---------------- single-pass decoupled-lookback scan + unbind ----------------
__global__ __launch_bounds__(128) void scan_fused() {
    __shared__ int sflag;
    int tid = threadIdx.x;
    int bidx = blockIdx.x;
    int chain = bidx >> 6;          // 0..19  = b*5 + fg
    int c = bidx & 63;
    int b = chain / 5;
    int fg = chain % 5;
    int f = fg * 128 + tid;
    bool active = (f < FF);
    int tok0 = b * LL + c * CHTOK;

    // phase 1: chunk aggregate
    float2 sum = make_float2(0.f, 0.f);
    if (active) {
#pragma unroll 4
        for (int tt = 0; tt < CHTOK; tt++) {
            float2 v = g_bf[(size_t)(tok0 + tt) * FF + f];
            sum.x += v.x; sum.y += v.y;
        }
    }

    if (c == 0) {
        if (active) g_pre[(size_t)bidx * 128 + tid] = sum;
        __threadfence();
        __syncthreads();
        if (tid == 0) atomicExch(&g_flag[bidx], 2);
    } else {
        if (active) g_agg[(size_t)bidx * 128 + tid] = sum;
        __threadfence();
        __syncthreads();
        if (tid == 0) atomicExch(&g_flag[bidx], 1);
    }

    // lookback for exclusive prefix
    float2 run = make_float2(0.f, 0.f);
    if (c > 0) {
        int look = bidx - 1;
        while (true) {
            if (tid == 0) {
                int fl;
                do { fl = atomicAdd(&g_flag[look], 0); } while (fl == 0);
                sflag = fl;
            }
            __syncthreads();
            int fl = sflag;
            __threadfence();
            if (active) {
                float2 p = (fl == 2) ? g_pre[(size_t)look * 128 + tid]
                                     : g_agg[(size_t)look * 128 + tid];
                run.x += p.x; run.y += p.y;
            }
            __syncthreads();
            if (fl == 2) break;
            look--;
        }
        if (active)
            g_pre[(size_t)bidx * 128 + tid] = make_float2(run.x + sum.x, run.y + sum.y);
        __threadfence();
        __syncthreads();
        if (tid == 0) atomicExch(&g_flag[bidx], 2);
    }

    // phase 2: cumsum + unbind rf = Mf * conj(Kf)  (chunk re-read mostly L2-hit)
    if (active) {
        float2 acc = run;
        for (int tt = 0; tt < CHTOK; tt++) {
            size_t idx = (size_t)(tok0 + tt) * FF + f;
            float2 v = g_bf[idx];
            acc.x += v.x; acc.y += v.y;
            float2 kf = g_kf[idx];
            g_bf[idx] = make_float2(acc.x*kf.x + acc.y*kf.y, acc.y*kf.x - acc.x*kf.y);
        }
    }
}

// ---------------- inverse: 512-pt complex IFFT + LN + bf16 hi/lo split -------
// 4 tokens per 512-thread block; 128 threads per token.
__global__ __launch_bounds__(512) void inv_kernel(const float* __restrict__ ln_g,
                                                  const float* __restrict__ ln_b) {
    __shared__ float2 sA[4][512];
    __shared__ float2 sB[4][512];
    __shared__ float2 rfny[4];
    __shared__ float red1[16];
    __shared__ float red2[16];
    int tid = threadIdx.x;
    int slot = tid >> 7;           // 0..3
    int ltid = tid & 127;
    int t = blockIdx.x * 4 + slot;
    int l = t % LL;

    const float2* rf = g_bf + (size_t)t * FF;
#pragma unroll
    for (int m = 0; m < 4; m++)
        sA[slot][ltid + 128*m] = rf[ltid + 128*m];
    if (ltid == 0) rfny[slot] = rf[512];
    __syncthreads();

    // Z[k] = 0.5*(X[k]+conj(X[512-k])) + 0.5*i*e^{+i*2pi*k/1024}*(X[k]-conj(X[512-k]))
#pragma unroll
    for (int m = 0; m < 4; m++) {
        int k = ltid + 128*m;
        float2 Xk = sA[slot][k];
        float2 Xm = (k == 0) ? rfny[slot] : sA[slot][512 - k];
        float2 sum = make_float2(Xk.x + Xm.x, Xk.y - Xm.y);
        float2 dif = make_float2(Xk.x - Xm.x, Xk.y + Xm.y);
        float2 wc = make_float2(g_tw[k].x, -g_tw[k].y);
        float2 t2 = cmul(wc, dif);
        sB[slot][k] = make_float2(0.5f*(sum.x - t2.y), 0.5f*(sum.y + t2.x));
    }
    __syncthreads();

    // inverse 512-pt FFT: 4 radix-4 stages + 1 radix-2 stage (conjugated twiddles)
    float2* src = sB[slot];
    float2* dst = sA[slot];
#pragma unroll
    for (int s = 0; s < 4; s++) {
        int Ns = 1 << (2*s);
        int j = ltid;
        int k = j & (Ns - 1);
        int twi = k << (8 - 2*s);
        float2 w1 = make_float2(g_tw[twi].x,   -g_tw[twi].y);
        float2 w2 = make_float2(g_tw[2*twi].x, -g_tw[2*twi].y);
        float2 w3 = make_float2(g_tw[3*twi].x, -g_tw[3*twi].y);
        float2 a = src[j];
        float2 b = cmul(src[j + 128], w1);
        float2 c = cmul(src[j + 256], w2);
        float2 d = cmul(src[j + 384], w3);
        float2 t0 = make_float2(a.x + c.x, a.y + c.y);
        float2 t1 = make_float2(a.x - c.x, a.y - c.y);
        float2 t2 = make_float2(b.x + d.x, b.y + d.y);
        float2 t3 = make_float2(d.y - b.y, b.x - d.x);   // +i*(b-d)
        int idx = ((j >> (2*s)) << (2*s + 2)) + k;
        dst[idx]        = make_float2(t0.x + t2.x, t0.y + t2.y);
        dst[idx + Ns]   = make_float2(t1.x + t3.x, t1.y + t3.y);
        dst[idx + 2*Ns] = make_float2(t0.x - t2.x, t0.y - t2.y);
        dst[idx + 3*Ns] = make_float2(t1.x - t3.x, t1.y - t3.y);
        __syncthreads();
        float2* tmp = src; src = dst; dst = tmp;
    }
    // radix-2 final stage
#pragma unroll
    for (int q = 0; q < 2; q++) {
        int j = ltid + 128*q;
        float2 w = make_float2(g_tw[2*j].x, -g_tw[2*j].y);
        float2 v0 = src[j];
        float2 v1 = src[j + 256];
        float2 tt = cmul(v1, w);
        dst[j]       = make_float2(v0.x + tt.x, v0.y + tt.y);
        dst[j + 256] = make_float2(v0.x - tt.x, v0.y - tt.y);
    }
    __syncthreads();
    float2* Z = dst;

    float s = (1.0f / 512.0f) * rsqrtf((float)(l + 1));
    float2 z0 = Z[2*ltid];
    float2 z1 = Z[2*ltid + 1];
    float2 z2 = Z[2*ltid + 256];
    float2 z3 = Z[2*ltid + 257];
    float xa0 = z0.x * s, xa1 = z0.y * s, xa2 = z1.x * s, xa3 = z1.y * s;
    float xb0 = z2.x * s, xb1 = z2.y * s, xb2 = z3.x * s, xb3 = z3.y * s;

    float sum = xa0 + xa1 + xa2 + xa3 + xb0 + xb1 + xb2 + xb3;
    float sq  = xa0*xa0 + xa1*xa1 + xa2*xa2 + xa3*xa3
              + xb0*xb0 + xb1*xb1 + xb2*xb2 + xb3*xb3;
#pragma unroll
    for (int o = 16; o; o >>= 1) {
        sum += __shfl_xor_sync(0xffffffffu, sum, o);
        sq  += __shfl_xor_sync(0xffffffffu, sq, o);
    }
    if ((tid & 31) == 0) { red1[tid >> 5] = sum; red2[tid >> 5] = sq; }
    __syncthreads();
    float tsum = 0.f, tsq = 0.f;
#pragma unroll
    for (int w = 0; w < 4; w++) { tsum += red1[slot*4 + w]; tsq += red2[slot*4 + w]; }
    float mu  = tsum * (1.0f / 1024.0f);
    float var = tsq * (1.0f / 1024.0f) - mu * mu;
    float inv = rsqrtf(var + 1e-5f);

    int colA = 4 * ltid;
    int colB = 512 + 4 * ltid;
    float4 gA = *reinterpret_cast<const float4*>(ln_g + colA);
    float4 bA = *reinterpret_cast<const float4*>(ln_b + colA);
    float4 gB = *reinterpret_cast<const float4*>(ln_g + colB);
    float4 bB = *reinterpret_cast<const float4*>(ln_b + colB);
    float rA[4], rB[4];
    rA[0] = (xa0 - mu) * inv * gA.x + bA.x;
    rA[1] = (xa1 - mu) * inv * gA.y + bA.y;
    rA[2] = (xa2 - mu) * inv * gA.z + bA.z;
    rA[3] = (xa3 - mu) * inv * gA.w + bA.w;
    rB[0] = (xb0 - mu) * inv * gB.x + bB.x;
    rB[1] = (xb1 - mu) * inv * gB.y + bB.y;
    rB[2] = (xb2 - mu) * inv * gB.z + bB.z;
    rB[3] = (xb3 - mu) * inv * gB.w + bB.w;

    size_t rowoff = (size_t)t * DD;
    __nv_bfloat16 hA[4], lA[4], hB[4], lB[4];
#pragma unroll
    for (int q = 0; q < 4; q++) {
        hA[q] = __float2bfloat16(rA[q]);
        lA[q] = __float2bfloat16(rA[q] - __bfloat162float(hA[q]));
        hB[q] = __float2bfloat16(rB[q]);
        lB[q] = __float2bfloat16(rB[q] - __bfloat162float(hB[q]));
    }
    __nv_bfloat162* hpA = reinterpret_cast<__nv_bfloat162*>(g_rhi + rowoff + colA);
    __nv_bfloat162* lpA = reinterpret_cast<__nv_bfloat162*>(g_rlo + rowoff + colA);
    __nv_bfloat162* hpB = reinterpret_cast<__nv_bfloat162*>(g_rhi + rowoff + colB);
    __nv_bfloat162* lpB = reinterpret_cast<__nv_bfloat162*>(g_rlo + rowoff + colB);
    hpA[0] = __halves2bfloat162(hA[0], hA[1]); hpA[1] = __halves2bfloat162(hA[2], hA[3]);
    lpA[0] = __halves2bfloat162(lA[0], lA[1]); lpA[1] = __halves2bfloat162(lA[2], lA[3]);
    hpB[0] = __halves2bfloat162(hB[0], hB[1]); hpB[1] = __halves2bfloat162(hB[2], hB[3]);
    lpB[0] = __halves2bfloat162(lB[0], lB[1]); lpB[1] = __halves2bfloat162(lB[2], lB[3]);
}

// ---------------- launch ------------------------------------------------------
extern "C" void kernel_launch(void* const* d_in, const int* in_sizes, int n_in,
                              void* d_out, int out_size) {
    const float* x    = (const float*)d_in[0];
    const float* Wk   = (const float*)d_in[1];
    const float* bk   = (const float*)d_in[2];
    const float* Wv   = (const float*)d_in[3];
    const float* bv   = (const float*)d_in[4];
    const float* ln_g = (const float*)d_in[5];
    const float* ln_b = (const float*)d_in[6];
    const float* Wo   = (const float*)d_in[7];
    const float* bo   = (const float*)d_in[8];
    float* out = (float*)d_out;

    void *p_kv;
    void *p_xhi, *p_xlo, *p_rhi, *p_rlo;
    void *p_wkvhi, *p_wkvlo, *p_wohi, *p_wolo, *p_bkv;
    cudaGetSymbolAddress(&p_kv,   g_kv);
    cudaGetSymbolAddress(&p_xhi,  g_xhi);
    cudaGetSymbolAddress(&p_xlo,  g_xlo);
    cudaGetSymbolAddress(&p_rhi,  g_rhi);
    cudaGetSymbolAddress(&p_rlo,  g_rlo);
    cudaGetSymbolAddress(&p_wkvhi, g_wkvhi);
    cudaGetSymbolAddress(&p_wkvlo, g_wkvlo);
    cudaGetSymbolAddress(&p_wohi, g_wohi);
    cudaGetSymbolAddress(&p_wolo, g_wolo);
    cudaGetSymbolAddress(&p_bkv,  g_bkv);

    cudaFuncSetAttribute(gemm_mma, cudaFuncAttributeMaxDynamicSharedMemorySize, GEMM_SMEM);

    setup_kernel<<<2, 1024>>>(bk, bv);

    int nx4 = MM * DD / 4;
    int nw4 = DD * DD / 4;
    split_conv<<<(nx4 + 255)/256, 256>>>(x, (__nv_bfloat16*)p_xhi, (__nv_bfloat16*)p_xlo, nx4);
    split_weights<<<(3*nw4 + 255)/256, 256>>>(Wk, Wv, Wo);

    // fused K+V projection: N = 2048
    dim3 kvgrid(2048 / BN, MM / BM);   // (16, 128)
    gemm_mma<<<kvgrid, 256, GEMM_SMEM>>>((__nv_bfloat16*)p_xhi, (__nv_bfloat16*)p_xlo,
                                         (__nv_bfloat16*)p_wkvhi, (__nv_bfloat16*)p_wkvlo,
                                         (const float*)p_bkv, nullptr, (float*)p_kv, 2048);

    fwd_kernel<<<MM/2, 512>>>();

    scan_fused<<<NBLK_SCAN, 128>>>();

    inv_kernel<<<MM/4, 512>>>(ln_g, ln_b);

    dim3 ogrid(DD / BN, MM / BM);      // (8, 128)
    gemm_mma<<<ogrid, 256, GEMM_SMEM>>>((__nv_bfloat16*)p_rhi, (__nv_bfloat16*)p_rlo,
                                        (__nv_bfloat16*)p_wohi, (__nv_bfloat16*)p_wolo,
                                        bo, x, out, DD);
}

// round 15
// speedup vs baseline: 1.0606x; 1.0325x over previous
#include <cuda_runtime.h>
#include <cuda_bf16.h>
#include <math.h>
#include <stdint.h>

// Problem constants
#define BB 4
#define LL 4096
#define DD 1024
#define MM (BB*LL)        // 16384 tokens
#define FF 513            // rfft bins for D=1024
#define NCHUNK 64
#define CHTOK (LL/NCHUNK) // 64 tokens per chunk
#define NBLK_SCAN (BB*5*NCHUNK)   // 1280

// ---------------- scratch (static device globals; no runtime alloc) ----------
__device__ float  g_kv[(size_t)MM*2048];   // keys cols 0..1023, vals 1024..2047
__device__ float2 g_kf[(size_t)MM*FF];
__device__ float2 g_bf[(size_t)MM*FF];
__device__ float2 g_tw[1024];              // exp(-2*pi*i*k/1024)

__device__ float2 g_agg[(size_t)NBLK_SCAN*128];
__device__ float2 g_pre[(size_t)NBLK_SCAN*128];
__device__ int    g_flag[NBLK_SCAN];

__device__ __nv_bfloat16 g_xhi[MM*DD];
__device__ __nv_bfloat16 g_xlo[MM*DD];
__device__ __nv_bfloat16 g_rhi[MM*DD];
__device__ __nv_bfloat16 g_rlo[MM*DD];
__device__ __nv_bfloat16 g_wkvhi[2*DD*DD]; // [Wk;Wv] stacked, 2048 x 1024
__device__ __nv_bfloat16 g_wkvlo[2*DD*DD];
__device__ __nv_bfloat16 g_wohi[DD*DD];
__device__ __nv_bfloat16 g_wolo[DD*DD];
__device__ float g_bkv[2048];

// ---------------- helpers ----------------------------------------------------
__device__ __forceinline__ float2 cmul(float2 a, float2 b) {
    return make_float2(a.x*b.x - a.y*b.y, a.x*b.y + a.y*b.x);
}

// merged setup: twiddles + bias concat + flag reset (grid 2 x 1024)
__global__ void setup_kernel(const float* __restrict__ bk, const float* __restrict__ bv) {
    int i = blockIdx.x * 1024 + threadIdx.x;   // 0..2047
    g_bkv[i] = (i < 1024) ? bk[i] : bv[i - 1024];
    if (blockIdx.x == 0) {
        int k = threadIdx.x;
        double ang = -2.0 * 3.14159265358979323846 * (double)k / 1024.0;
        g_tw[k] = make_float2((float)cos(ang), (float)sin(ang));
    }
    if (i < NBLK_SCAN) g_flag[i] = 0;
}

// ---------------- fp32 -> bf16 hi/lo split ------------------------------------
__device__ __forceinline__ void split4(const float* __restrict__ in,
    __nv_bfloat16* __restrict__ hi, __nv_bfloat16* __restrict__ lo, int i)
{
    float4 v = reinterpret_cast<const float4*>(in)[i];
    __nv_bfloat16 h0 = __float2bfloat16(v.x);
    __nv_bfloat16 h1 = __float2bfloat16(v.y);
    __nv_bfloat16 h2 = __float2bfloat16(v.z);
    __nv_bfloat16 h3 = __float2bfloat16(v.w);
    __nv_bfloat16 l0 = __float2bfloat16(v.x - __bfloat162float(h0));
    __nv_bfloat16 l1 = __float2bfloat16(v.y - __bfloat162float(h1));
    __nv_bfloat16 l2 = __float2bfloat16(v.z - __bfloat162float(h2));
    __nv_bfloat16 l3 = __float2bfloat16(v.w - __bfloat162float(h3));
    __nv_bfloat162* hp = reinterpret_cast<__nv_bfloat162*>(hi) + 2*(size_t)i;
    __nv_bfloat162* lp = reinterpret_cast<__nv_bfloat162*>(lo) + 2*(size_t)i;
    hp[0] = __halves2bfloat162(h0, h1);
    hp[1] = __halves2bfloat162(h2, h3);
    lp[0] = __halves2bfloat162(l0, l1);
    lp[1] = __halves2bfloat162(l2, l3);
}

__global__ __launch_bounds__(256) void split_conv(const float* __restrict__ in,
    __nv_bfloat16* __restrict__ hi, __nv_bfloat16* __restrict__ lo, int n4)
{
    int i = blockIdx.x * 256 + threadIdx.x;
    if (i >= n4) return;
    split4(in, hi, lo, i);
}

// fused weight split: Wk, Wv -> wkv (stacked), Wo -> wo. 3072 blocks.
__global__ __launch_bounds__(256) void split_weights(
    const float* __restrict__ Wk, const float* __restrict__ Wv, const float* __restrict__ Wo)
{
    int nw4 = DD * DD / 4;           // 262144
    int gi = blockIdx.x * 256 + threadIdx.x;
    if (gi < nw4) {
        split4(Wk, g_wkvhi, g_wkvlo, gi);
    } else if (gi < 2 * nw4) {
        split4(Wv, g_wkvhi + (size_t)DD*DD, g_wkvlo + (size_t)DD*DD, gi - nw4);
    } else {
        split4(Wo, g_wohi, g_wolo, gi - 2 * nw4);
    }
}

// ---------------- mma.sync GEMM (portable PTX) --------------------------------
// R12-proven: 128x128 CTA tile, 8 warps (4Mx2N), BK=64, 3 stages, 2 CTA/SM.
#define BM 128
#define BN 128
#define BK 64
#define NSTG 3
#define NIT 48                          // 3 segments * 16 iters of K=64
#define STG_BYTES ((BM*BK + BN*BK)*2)   // 32768
#define GEMM_SMEM (NSTG*STG_BYTES)      // 98304

__device__ __forceinline__ uint32_t s2u(const void* p) {
    uint32_t a;
    asm("{ .reg .u64 t; cvta.to.shared.u64 t, %1; cvt.u32.u64 %0, t; }" : "=r"(a) : "l"(p));
    return a;
}
// BK=64: each row is exactly 128B = one SW128 line. kc = 16B chunk (0..7).
__device__ __forceinline__ uint32_t tile_off(int row, int kc) {
    uint32_t off = (uint32_t)row * 128u + (uint32_t)(kc * 16);
    return off ^ ((off >> 3) & 0x70);
}
__device__ __forceinline__ void cp16(uint32_t dst, const void* src) {
    asm volatile("cp.async.cg.shared.global [%0], [%1], 16;" :: "r"(dst), "l"(src));
}
__device__ __forceinline__ void cp_commit() {
    asm volatile("cp.async.commit_group;" ::: "memory");
}
__device__ __forceinline__ void cp_wait(int n) {
    if (n >= 1) asm volatile("cp.async.wait_group 1;" ::: "memory");
    else        asm volatile("cp.async.wait_group 0;" ::: "memory");
}
__device__ __forceinline__ void ldm4(uint32_t* r, uint32_t addr) {
    asm volatile("ldmatrix.sync.aligned.m8n8.x4.shared.b16 {%0,%1,%2,%3}, [%4];"
                 : "=r"(r[0]), "=r"(r[1]), "=r"(r[2]), "=r"(r[3]) : "r"(addr));
}
__device__ __forceinline__ void mma16816(float* c, const uint32_t* a, uint32_t b0, uint32_t b1) {
    asm volatile(
        "mma.sync.aligned.m16n8k16.row.col.f32.bf16.bf16.f32 "
        "{%0,%1,%2,%3}, {%4,%5,%6,%7}, {%8,%9}, {%0,%1,%2,%3};"
        : "+f"(c[0]), "+f"(c[1]), "+f"(c[2]), "+f"(c[3])
        : "r"(a[0]), "r"(a[1]), "r"(a[2]), "r"(a[3]), "r"(b0), "r"(b1));
}

__global__ __launch_bounds__(256) void gemm_mma(
    const __nv_bfloat16* __restrict__ Ahi, const __nv_bfloat16* __restrict__ Alo,
    const __nv_bfloat16* __restrict__ Bhi, const __nv_bfloat16* __restrict__ Blo,
    const float* __restrict__ bias, const float* __restrict__ res,
    float* __restrict__ out, int ldout)
{
    extern __shared__ char smem[];
    uint32_t sb = s2u(smem);
    int tid = threadIdx.x;
    int wid = tid >> 5, lane = tid & 31;
    int bm = blockIdx.y * BM, bn = blockIdx.x * BN;
    int wm = (wid & 3) * 32;
    int wn = (wid >> 2) * 64;

    const __nv_bfloat16* Asrc[3] = {Ahi, Ahi, Alo};
    const __nv_bfloat16* Bsrc[3] = {Bhi, Blo, Bhi};

    uint32_t offA[2][4], offB[4][4];
#pragma unroll
    for (int mt = 0; mt < 2; mt++)
#pragma unroll
        for (int ks = 0; ks < 4; ks++) {
            int row = wm + mt*16 + (lane & 7) + ((lane >> 3) & 1) * 8;
            int kc  = ks*2 + (lane >> 4);
            offA[mt][ks] = tile_off(row, kc);
        }
#pragma unroll
    for (int p = 0; p < 4; p++)
#pragma unroll
        for (int ks = 0; ks < 4; ks++) {
            int row = wn + p*16 + (lane & 7) + (lane >> 4) * 8;
            int kc  = ks*2 + ((lane >> 3) & 1);
            offB[p][ks] = tile_off(row, kc);
        }

    float acc[2][8][4];
#pragma unroll
    for (int mt = 0; mt < 2; mt++)
#pragma unroll
        for (int nt = 0; nt < 8; nt++)
#pragma unroll
            for (int q = 0; q < 4; q++) acc[mt][nt][q] = 0.0f;

    auto load_stage = [&](int slot, int iter) {
        int seg = iter >> 4;
        int k0  = (iter & 15) * BK;
        const __nv_bfloat16* A = Asrc[seg];
        const __nv_bfloat16* B = Bsrc[seg];
        uint32_t abase = sb + slot * STG_BYTES;
        uint32_t bbase = abase + BM * BK * 2;
#pragma unroll
        for (int j = 0; j < 4; j++) {
            int idx = tid + j * 256;
            int row = idx >> 3, c = idx & 7;
            cp16(abase + tile_off(row, c), A + (size_t)(bm + row) * DD + k0 + c * 8);
        }
#pragma unroll
        for (int j = 0; j < 4; j++) {
            int idx = tid + j * 256;
            int row = idx >> 3, c = idx & 7;
            cp16(bbase + tile_off(row, c), B + (size_t)(bn + row) * DD + k0 + c * 8);
        }
        cp_commit();
    };

#pragma unroll
    for (int s = 0; s < NSTG - 1; s++) load_stage(s, s);

    for (int i = 0; i < NIT; i++) {
        int slot = i % NSTG;
        int pend = NIT - 1 - i; if (pend > NSTG - 2) pend = NSTG - 2;
        cp_wait(pend);
        __syncthreads();

        uint32_t abase = sb + slot * STG_BYTES;
        uint32_t bbase = abase + BM * BK * 2;
#pragma unroll
        for (int ks = 0; ks < 4; ks++) {
            uint32_t a[2][4], b[4][4];
#pragma unroll
            for (int mt = 0; mt < 2; mt++) ldm4(a[mt], abase + offA[mt][ks]);
#pragma unroll
            for (int p = 0; p < 4; p++)    ldm4(b[p], bbase + offB[p][ks]);
#pragma unroll
            for (int mt = 0; mt < 2; mt++)
#pragma unroll
                for (int nt = 0; nt < 8; nt++)
                    mma16816(acc[mt][nt], a[mt], b[nt >> 1][(nt & 1) * 2], b[nt >> 1][(nt & 1) * 2 + 1]);
        }

        if (i + NSTG - 1 < NIT)
            load_stage((i + NSTG - 1) % NSTG, i + NSTG - 1);
    }

    int qr = lane >> 2, qc = (lane & 3) * 2;
#pragma unroll
    for (int mt = 0; mt < 2; mt++) {
#pragma unroll
        for (int nt = 0; nt < 8; nt++) {
            int col = bn + wn + nt * 8 + qc;
            float b0 = bias[col], b1 = bias[col + 1];
            int r0 = bm + wm + mt * 16 + qr;
            size_t g0 = (size_t)r0 * ldout + col;
            size_t g1 = g0 + (size_t)8 * ldout;
            float2 v0 = make_float2(acc[mt][nt][0] + b0, acc[mt][nt][1] + b1);
            float2 v1 = make_float2(acc[mt][nt][2] + b0, acc[mt][nt][3] + b1);
            if (res) {
                float2 x0 = *reinterpret_cast<const float2*>(res + g0);
                float2 x1 = *reinterpret_cast<const float2*>(res + g1);
                v0.x += x0.x; v0.y += x0.y;
                v1.x += x1.x; v1.y += x1.y;
            }
            *reinterpret_cast<float2*>(out + g0) = v0;
            *reinterpret_cast<float2*>(out + g1) = v1;
        }
    }
}

// ---------------- forward: norm keys, radix-4 FFT(k+iv), Kf & Kf*Vf ----------
// 2 tokens per 256-thread block; 128 threads per token, 2 butterflies/thread.
__global__ __launch_bounds__(256) void fwd_kernel() {
    __shared__ float2 sA[2][1024];
    __shared__ float2 sB[2][1024];
    __shared__ float red[8];
    int tid = threadIdx.x;
    int slot = tid >> 7;          // 0..1
    int ltid = tid & 127;
    int t = blockIdx.x * 2 + slot;

    const float* krow = g_kv + (size_t)t * 2048;
    const float* vrow = krow + 1024;
    float kx[8], vx[8];
#pragma unroll
    for (int m = 0; m < 8; m++) {
        kx[m] = krow[ltid + 128*m];
        vx[m] = vrow[ltid + 128*m];
    }

    float ss = 0.f;
#pragma unroll
    for (int m = 0; m < 8; m++) ss += kx[m]*kx[m];
#pragma unroll
    for (int o = 16; o; o >>= 1) ss += __shfl_xor_sync(0xffffffffu, ss, o);
    if ((tid & 31) == 0) red[tid >> 5] = ss;
    __syncthreads();
    float tot = red[slot*4] + red[slot*4+1] + red[slot*4+2] + red[slot*4+3];
    float scale = 1.0f / fmaxf(sqrtf(tot), 1e-12f);

#pragma unroll
    for (int m = 0; m < 8; m++)
        sA[slot][ltid + 128*m] = make_float2(kx[m]*scale, vx[m]);
    __syncthreads();

    // 5 radix-4 Stockham stages, N=1024, 2 butterflies per thread
    float2* src = sA[slot];
    float2* dst = sB[slot];
#pragma unroll
    for (int s = 0; s < 5; s++) {
        int Ns = 1 << (2*s);
#pragma unroll
        for (int q = 0; q < 2; q++) {
            int j = ltid + 128*q;
            int k = j & (Ns - 1);
            int twi = k << (8 - 2*s);          // 256*k/Ns
            float2 w1 = g_tw[twi];
            float2 w2 = g_tw[2*twi];
            float2 w3 = g_tw[3*twi];
            float2 a = src[j];
            float2 b = cmul(src[j + 256], w1);
            float2 c = cmul(src[j + 512], w2);
            float2 d = cmul(src[j + 768], w3);
            float2 t0 = make_float2(a.x + c.x, a.y + c.y);
            float2 t1 = make_float2(a.x - c.x, a.y - c.y);
            float2 t2 = make_float2(b.x + d.x, b.y + d.y);
            float2 t3 = make_float2(b.y - d.y, d.x - b.x);   // -i*(b-d)
            int idx = ((j >> (2*s)) << (2*s + 2)) + k;
            dst[idx]        = make_float2(t0.x + t2.x, t0.y + t2.y);
            dst[idx + Ns]   = make_float2(t1.x + t3.x, t1.y + t3.y);
            dst[idx + 2*Ns] = make_float2(t0.x - t2.x, t0.y - t2.y);
            dst[idx + 3*Ns] = make_float2(t1.x - t3.x, t1.y - t3.y);
        }
        __syncthreads();
        float2* tmp = src; src = dst; dst = tmp;
    }
    // result in src

#pragma unroll
    for (int e = 0; e < 4; e++) {
        int f = ltid + 128*e;            // 0..511
        float2 Zf = src[f];
        float2 Zn = src[(1024 - f) & 1023];
        float2 Kf = make_float2(0.5f*(Zf.x + Zn.x), 0.5f*(Zf.y - Zn.y));
        float2 Vf = make_float2(0.5f*(Zf.y + Zn.y), 0.5f*(Zn.x - Zf.x));
        size_t idx = (size_t)t * FF + f;
        g_kf[idx] = Kf;
        g_bf[idx] = cmul(Kf, Vf);
    }
    if (ltid == 0) {
        float2 Zf = src[512];
        // f = 512: Zn = src[512] as well -> Kf = (Re Zf, 0) ... use general form
        float2 Kf = make_float2(Zf.x, 0.0f);
        float2 Vf = make_float2(Zf.y, 0.0f);
        size_t idx = (size_t)t * FF + 512;
        g_kf[idx] = Kf;
        g_bf[idx] = cmul(Kf, Vf);
    }
}

// ---------------- single-pass decoupled-lookback scan + unbind ----------------
__global__ __launch_bounds__(128) void scan_fused() {
    __shared__ int sflag;
    int tid = threadIdx.x;
    int bidx = blockIdx.x;
    int chain = bidx >> 6;          // 0..19  = b*5 + fg
    int c = bidx & 63;
    int b = chain / 5;
    int fg = chain % 5;
    int f = fg * 128 + tid;
    bool active = (f < FF);
    int tok0 = b * LL + c * CHTOK;

    // phase 1: chunk aggregate
    float2 sum = make_float2(0.f, 0.f);
    if (active) {
#pragma unroll 4
        for (int tt = 0; tt < CHTOK; tt++) {
            float2 v = g_bf[(size_t)(tok0 + tt) * FF + f];
            sum.x += v.x; sum.y += v.y;
        }
    }

    if (c == 0) {
        if (active) g_pre[(size_t)bidx * 128 + tid] = sum;
        __threadfence();
        __syncthreads();
        if (tid == 0) atomicExch(&g_flag[bidx], 2);
    } else {
        if (active) g_agg[(size_t)bidx * 128 + tid] = sum;
        __threadfence();
        __syncthreads();
        if (tid == 0) atomicExch(&g_flag[bidx], 1);
    }

    // lookback for exclusive prefix
    float2 run = make_float2(0.f, 0.f);
    if (c > 0) {
        int look = bidx - 1;
        while (true) {
            if (tid == 0) {
                int fl;
                do { fl = atomicAdd(&g_flag[look], 0); } while (fl == 0);
                sflag = fl;
            }
            __syncthreads();
            int fl = sflag;
            __threadfence();
            if (active) {
                float2 p = (fl == 2) ? g_pre[(size_t)look * 128 + tid]
                                     : g_agg[(size_t)look * 128 + tid];
                run.x += p.x; run.y += p.y;
            }
            __syncthreads();
            if (fl == 2) break;
            look--;
        }
        if (active)
            g_pre[(size_t)bidx * 128 + tid] = make_float2(run.x + sum.x, run.y + sum.y);
        __threadfence();
        __syncthreads();
        if (tid == 0) atomicExch(&g_flag[bidx], 2);
    }

    // phase 2: cumsum + unbind rf = Mf * conj(Kf)  (chunk re-read mostly L2-hit)
    if (active) {
        float2 acc = run;
        for (int tt = 0; tt < CHTOK; tt++) {
            size_t idx = (size_t)(tok0 + tt) * FF + f;
            float2 v = g_bf[idx];
            acc.x += v.x; acc.y += v.y;
            float2 kf = g_kf[idx];
            g_bf[idx] = make_float2(acc.x*kf.x + acc.y*kf.y, acc.y*kf.x - acc.x*kf.y);
        }
    }
}

// ---------------- inverse: 512-pt complex IFFT + LN + bf16 hi/lo split -------
// 4 tokens per 512-thread block; 128 threads per token.
__global__ __launch_bounds__(512) void inv_kernel(const float* __restrict__ ln_g,
                                                  const float* __restrict__ ln_b) {
    __shared__ float2 sA[4][512];
    __shared__ float2 sB[4][512];
    __shared__ float2 rfny[4];
    __shared__ float red1[16];
    __shared__ float red2[16];
    int tid = threadIdx.x;
    int slot = tid >> 7;           // 0..3
    int ltid = tid & 127;
    int t = blockIdx.x * 4 + slot;
    int l = t % LL;

    const float2* rf = g_bf + (size_t)t * FF;
#pragma unroll
    for (int m = 0; m < 4; m++)
        sA[slot][ltid + 128*m] = rf[ltid + 128*m];
    if (ltid == 0) rfny[slot] = rf[512];
    __syncthreads();

    // Z[k] = 0.5*(X[k]+conj(X[512-k])) + 0.5*i*e^{+i*2pi*k/1024}*(X[k]-conj(X[512-k]))
#pragma unroll
    for (int m = 0; m < 4; m++) {
        int k = ltid + 128*m;
        float2 Xk = sA[slot][k];
        float2 Xm = (k == 0) ? rfny[slot] : sA[slot][512 - k];
        float2 sum = make_float2(Xk.x + Xm.x, Xk.y - Xm.y);
        float2 dif = make_float2(Xk.x - Xm.x, Xk.y + Xm.y);
        float2 wc = make_float2(g_tw[k].x, -g_tw[k].y);
        float2 t2 = cmul(wc, dif);
        sB[slot][k] = make_float2(0.5f*(sum.x - t2.y), 0.5f*(sum.y + t2.x));
    }
    __syncthreads();

    // inverse 512-pt FFT: 4 radix-4 stages + 1 radix-2 stage (conjugated twiddles)
    float2* src = sB[slot];
    float2* dst = sA[slot];
#pragma unroll
    for (int s = 0; s < 4; s++) {
        int Ns = 1 << (2*s);
        int j = ltid;
        int k = j & (Ns - 1);
        int twi = k << (8 - 2*s);
        float2 w1 = make_float2(g_tw[twi].x,   -g_tw[twi].y);
        float2 w2 = make_float2(g_tw[2*twi].x, -g_tw[2*twi].y);
        float2 w3 = make_float2(g_tw[3*twi].x, -g_tw[3*twi].y);
        float2 a = src[j];
        float2 b = cmul(src[j + 128], w1);
        float2 c = cmul(src[j + 256], w2);
        float2 d = cmul(src[j + 384], w3);
        float2 t0 = make_float2(a.x + c.x, a.y + c.y);
        float2 t1 = make_float2(a.x - c.x, a.y - c.y);
        float2 t2 = make_float2(b.x + d.x, b.y + d.y);
        float2 t3 = make_float2(d.y - b.y, b.x - d.x);   // +i*(b-d)
        int idx = ((j >> (2*s)) << (2*s + 2)) + k;
        dst[idx]        = make_float2(t0.x + t2.x, t0.y + t2.y);
        dst[idx + Ns]   = make_float2(t1.x + t3.x, t1.y + t3.y);
        dst[idx + 2*Ns] = make_float2(t0.x - t2.x, t0.y - t2.y);
        dst[idx + 3*Ns] = make_float2(t1.x - t3.x, t1.y - t3.y);
        __syncthreads();
        float2* tmp = src; src = dst; dst = tmp;
    }
    // radix-2 final stage
#pragma unroll
    for (int q = 0; q < 2; q++) {
        int j = ltid + 128*q;
        float2 w = make_float2(g_tw[2*j].x, -g_tw[2*j].y);
        float2 v0 = src[j];
        float2 v1 = src[j + 256];
        float2 tt = cmul(v1, w);
        dst[j]       = make_float2(v0.x + tt.x, v0.y + tt.y);
        dst[j + 256] = make_float2(v0.x - tt.x, v0.y - tt.y);
    }
    __syncthreads();
    float2* Z = dst;

    float s = (1.0f / 512.0f) * rsqrtf((float)(l + 1));
    float2 z0 = Z[2*ltid];
    float2 z1 = Z[2*ltid + 1];
    float2 z2 = Z[2*ltid + 256];
    float2 z3 = Z[2*ltid + 257];
    float xa0 = z0.x * s, xa1 = z0.y * s, xa2 = z1.x * s, xa3 = z1.y * s;
    float xb0 = z2.x * s, xb1 = z2.y * s, xb2 = z3.x * s, xb3 = z3.y * s;

    float sum = xa0 + xa1 + xa2 + xa3 + xb0 + xb1 + xb2 + xb3;
    float sq  = xa0*xa0 + xa1*xa1 + xa2*xa2 + xa3*xa3
              + xb0*xb0 + xb1*xb1 + xb2*xb2 + xb3*xb3;
#pragma unroll
    for (int o = 16; o; o >>= 1) {
        sum += __shfl_xor_sync(0xffffffffu, sum, o);
        sq  += __shfl_xor_sync(0xffffffffu, sq, o);
    }
    if ((tid & 31) == 0) { red1[tid >> 5] = sum; red2[tid >> 5] = sq; }
    __syncthreads();
    float tsum = 0.f, tsq = 0.f;
#pragma unroll
    for (int w = 0; w < 4; w++) { tsum += red1[slot*4 + w]; tsq += red2[slot*4 + w]; }
    float mu  = tsum * (1.0f / 1024.0f);
    float var = tsq * (1.0f / 1024.0f) - mu * mu;
    float inv = rsqrtf(var + 1e-5f);

    int colA = 4 * ltid;
    int colB = 512 + 4 * ltid;
    float4 gA = *reinterpret_cast<const float4*>(ln_g + colA);
    float4 bA = *reinterpret_cast<const float4*>(ln_b + colA);
    float4 gB = *reinterpret_cast<const float4*>(ln_g + colB);
    float4 bB = *reinterpret_cast<const float4*>(ln_b + colB);
    float rA[4], rB[4];
    rA[0] = (xa0 - mu) * inv * gA.x + bA.x;
    rA[1] = (xa1 - mu) * inv * gA.y + bA.y;
    rA[2] = (xa2 - mu) * inv * gA.z + bA.z;
    rA[3] = (xa3 - mu) * inv * gA.w + bA.w;
    rB[0] = (xb0 - mu) * inv * gB.x + bB.x;
    rB[1] = (xb1 - mu) * inv * gB.y + bB.y;
    rB[2] = (xb2 - mu) * inv * gB.z + bB.z;
    rB[3] = (xb3 - mu) * inv * gB.w + bB.w;

    size_t rowoff = (size_t)t * DD;
    __nv_bfloat16 hA[4], lA[4], hB[4], lB[4];
#pragma unroll
    for (int q = 0; q < 4; q++) {
        hA[q] = __float2bfloat16(rA[q]);
        lA[q] = __float2bfloat16(rA[q] - __bfloat162float(hA[q]));
        hB[q] = __float2bfloat16(rB[q]);
        lB[q] = __float2bfloat16(rB[q] - __bfloat162float(hB[q]));
    }
    __nv_bfloat162* hpA = reinterpret_cast<__nv_bfloat162*>(g_rhi + rowoff + colA);
    __nv_bfloat162* lpA = reinterpret_cast<__nv_bfloat162*>(g_rlo + rowoff + colA);
    __nv_bfloat162* hpB = reinterpret_cast<__nv_bfloat162*>(g_rhi + rowoff + colB);
    __nv_bfloat162* lpB = reinterpret_cast<__nv_bfloat162*>(g_rlo + rowoff + colB);
    hpA[0] = __halves2bfloat162(hA[0], hA[1]); hpA[1] = __halves2bfloat162(hA[2], hA[3]);
    lpA[0] = __halves2bfloat162(lA[0], lA[1]); lpA[1] = __halves2bfloat162(lA[2], lA[3]);
    hpB[0] = __halves2bfloat162(hB[0], hB[1]); hpB[1] = __halves2bfloat162(hB[2], hB[3]);
    lpB[0] = __halves2bfloat162(lB[0], lB[1]); lpB[1] = __halves2bfloat162(lB[2], lB[3]);
}

// ---------------- launch ------------------------------------------------------
extern "C" void kernel_launch(void* const* d_in, const int* in_sizes, int n_in,
                              void* d_out, int out_size) {
    const float* x    = (const float*)d_in[0];
    const float* Wk   = (const float*)d_in[1];
    const float* bk   = (const float*)d_in[2];
    const float* Wv   = (const float*)d_in[3];
    const float* bv   = (const float*)d_in[4];
    const float* ln_g = (const float*)d_in[5];
    const float* ln_b = (const float*)d_in[6];
    const float* Wo   = (const float*)d_in[7];
    const float* bo   = (const float*)d_in[8];
    float* out = (float*)d_out;

    void *p_kv;
    void *p_xhi, *p_xlo, *p_rhi, *p_rlo;
    void *p_wkvhi, *p_wkvlo, *p_wohi, *p_wolo, *p_bkv;
    cudaGetSymbolAddress(&p_kv,   g_kv);
    cudaGetSymbolAddress(&p_xhi,  g_xhi);
    cudaGetSymbolAddress(&p_xlo,  g_xlo);
    cudaGetSymbolAddress(&p_rhi,  g_rhi);
    cudaGetSymbolAddress(&p_rlo,  g_rlo);
    cudaGetSymbolAddress(&p_wkvhi, g_wkvhi);
    cudaGetSymbolAddress(&p_wkvlo, g_wkvlo);
    cudaGetSymbolAddress(&p_wohi, g_wohi);
    cudaGetSymbolAddress(&p_wolo, g_wolo);
    cudaGetSymbolAddress(&p_bkv,  g_bkv);

    cudaFuncSetAttribute(gemm_mma, cudaFuncAttributeMaxDynamicSharedMemorySize, GEMM_SMEM);

    setup_kernel<<<2, 1024>>>(bk, bv);

    int nx4 = MM * DD / 4;
    int nw4 = DD * DD / 4;
    split_conv<<<(nx4 + 255)/256, 256>>>(x, (__nv_bfloat16*)p_xhi, (__nv_bfloat16*)p_xlo, nx4);
    split_weights<<<(3*nw4 + 255)/256, 256>>>(Wk, Wv, Wo);

    // fused K+V projection: N = 2048
    dim3 kvgrid(2048 / BN, MM / BM);   // (16, 128)
    gemm_mma<<<kvgrid, 256, GEMM_SMEM>>>((__nv_bfloat16*)p_xhi, (__nv_bfloat16*)p_xlo,
                                         (__nv_bfloat16*)p_wkvhi, (__nv_bfloat16*)p_wkvlo,
                                         (const float*)p_bkv, nullptr, (float*)p_kv, 2048);

    fwd_kernel<<<MM/2, 256>>>();

    scan_fused<<<NBLK_SCAN, 128>>>();

    inv_kernel<<<MM/4, 512>>>(ln_g, ln_b);

    dim3 ogrid(DD / BN, MM / BM);      // (8, 128)
    gemm_mma<<<ogrid, 256, GEMM_SMEM>>>((__nv_bfloat16*)p_rhi, (__nv_bfloat16*)p_rlo,
                                        (__nv_bfloat16*)p_wohi, (__nv_bfloat16*)p_wolo,
                                        bo, x, out, DD);
}

// round 16
// speedup vs baseline: 1.0793x; 1.0177x over previous
#include <cuda_runtime.h>
#include <cuda_bf16.h>
#include <math.h>
#include <stdint.h>

// Problem constants
#define BB 4
#define LL 4096
#define DD 1024
#define MM (BB*LL)        // 16384 tokens
#define FF 513            // rfft bins for D=1024
#define NCHUNK 64
#define CHTOK (LL/NCHUNK) // 64 tokens per chunk
#define NBLK_SCAN (BB*5*NCHUNK)   // 1280

// ---------------- scratch (static device globals; no runtime alloc) ----------
__device__ float  g_kv[(size_t)MM*2048];   // keys cols 0..1023, vals 1024..2047
__device__ float2 g_kf[(size_t)MM*FF];
__device__ float2 g_bf[(size_t)MM*FF];
__device__ float2 g_tw[1024];              // exp(-2*pi*i*k/1024)

__device__ float2 g_agg[(size_t)NBLK_SCAN*128];
__device__ float2 g_pre[(size_t)NBLK_SCAN*128];
__device__ int    g_flag[NBLK_SCAN];

__device__ __nv_bfloat16 g_xhi[MM*DD];
__device__ __nv_bfloat16 g_xlo[MM*DD];
__device__ __nv_bfloat16 g_rhi[MM*DD];
__device__ __nv_bfloat16 g_rlo[MM*DD];
__device__ __nv_bfloat16 g_wkvhi[2*DD*DD]; // [Wk;Wv] stacked, 2048 x 1024
__device__ __nv_bfloat16 g_wkvlo[2*DD*DD];
__device__ __nv_bfloat16 g_wohi[DD*DD];
__device__ __nv_bfloat16 g_wolo[DD*DD];
__device__ float g_bkv[2048];

// ---------------- helpers ----------------------------------------------------
__device__ __forceinline__ float2 cmul(float2 a, float2 b) {
    return make_float2(a.x*b.x - a.y*b.y, a.x*b.y + a.y*b.x);
}

// merged setup: twiddles + bias concat + flag reset (grid 2 x 1024)
__global__ void setup_kernel(const float* __restrict__ bk, const float* __restrict__ bv) {
    int i = blockIdx.x * 1024 + threadIdx.x;   // 0..2047
    g_bkv[i] = (i < 1024) ? bk[i] : bv[i - 1024];
    if (blockIdx.x == 0) {
        int k = threadIdx.x;
        double ang = -2.0 * 3.14159265358979323846 * (double)k / 1024.0;
        g_tw[k] = make_float2((float)cos(ang), (float)sin(ang));
    }
    if (i < NBLK_SCAN) g_flag[i] = 0;
}

// ---------------- fp32 -> bf16 hi/lo split ------------------------------------
__device__ __forceinline__ void split4(const float* __restrict__ in,
    __nv_bfloat16* __restrict__ hi, __nv_bfloat16* __restrict__ lo, int i)
{
    float4 v = reinterpret_cast<const float4*>(in)[i];
    __nv_bfloat16 h0 = __float2bfloat16(v.x);
    __nv_bfloat16 h1 = __float2bfloat16(v.y);
    __nv_bfloat16 h2 = __float2bfloat16(v.z);
    __nv_bfloat16 h3 = __float2bfloat16(v.w);
    __nv_bfloat16 l0 = __float2bfloat16(v.x - __bfloat162float(h0));
    __nv_bfloat16 l1 = __float2bfloat16(v.y - __bfloat162float(h1));
    __nv_bfloat16 l2 = __float2bfloat16(v.z - __bfloat162float(h2));
    __nv_bfloat16 l3 = __float2bfloat16(v.w - __bfloat162float(h3));
    __nv_bfloat162* hp = reinterpret_cast<__nv_bfloat162*>(hi) + 2*(size_t)i;
    __nv_bfloat162* lp = reinterpret_cast<__nv_bfloat162*>(lo) + 2*(size_t)i;
    hp[0] = __halves2bfloat162(h0, h1);
    hp[1] = __halves2bfloat162(h2, h3);
    lp[0] = __halves2bfloat162(l0, l1);
    lp[1] = __halves2bfloat162(l2, l3);
}

__global__ __launch_bounds__(256) void split_conv(const float* __restrict__ in,
    __nv_bfloat16* __restrict__ hi, __nv_bfloat16* __restrict__ lo, int n4)
{
    int i = blockIdx.x * 256 + threadIdx.x;
    if (i >= n4) return;
    split4(in, hi, lo, i);
}

// fused weight split: Wk, Wv -> wkv (stacked), Wo -> wo. 3072 blocks.
__global__ __launch_bounds__(256) void split_weights(
    const float* __restrict__ Wk, const float* __restrict__ Wv, const float* __restrict__ Wo)
{
    int nw4 = DD * DD / 4;           // 262144
    int gi = blockIdx.x * 256 + threadIdx.x;
    if (gi < nw4) {
        split4(Wk, g_wkvhi, g_wkvlo, gi);
    } else if (gi < 2 * nw4) {
        split4(Wv, g_wkvhi + (size_t)DD*DD, g_wkvlo + (size_t)DD*DD, gi - nw4);
    } else {
        split4(Wo, g_wohi, g_wolo, gi - 2 * nw4);
    }
}

// ---------------- mma.sync GEMM (portable PTX) --------------------------------
// R12-proven: 128x128 CTA tile, 8 warps (4Mx2N), BK=64, 3 stages, 2 CTA/SM.
#define BM 128
#define BN 128
#define BK 64
#define NSTG 3
#define NIT 48                          // 3 segments * 16 iters of K=64
#define STG_BYTES ((BM*BK + BN*BK)*2)   // 32768
#define GEMM_SMEM (NSTG*STG_BYTES)      // 98304

__device__ __forceinline__ uint32_t s2u(const void* p) {
    uint32_t a;
    asm("{ .reg .u64 t; cvta.to.shared.u64 t, %1; cvt.u32.u64 %0, t; }" : "=r"(a) : "l"(p));
    return a;
}
// BK=64: each row is exactly 128B = one SW128 line. kc = 16B chunk (0..7).
__device__ __forceinline__ uint32_t tile_off(int row, int kc) {
    uint32_t off = (uint32_t)row * 128u + (uint32_t)(kc * 16);
    return off ^ ((off >> 3) & 0x70);
}
__device__ __forceinline__ void cp16(uint32_t dst, const void* src) {
    asm volatile("cp.async.cg.shared.global [%0], [%1], 16;" :: "r"(dst), "l"(src));
}
__device__ __forceinline__ void cp_commit() {
    asm volatile("cp.async.commit_group;" ::: "memory");
}
__device__ __forceinline__ void cp_wait(int n) {
    if (n >= 1) asm volatile("cp.async.wait_group 1;" ::: "memory");
    else        asm volatile("cp.async.wait_group 0;" ::: "memory");
}
__device__ __forceinline__ void ldm4(uint32_t* r, uint32_t addr) {
    asm volatile("ldmatrix.sync.aligned.m8n8.x4.shared.b16 {%0,%1,%2,%3}, [%4];"
                 : "=r"(r[0]), "=r"(r[1]), "=r"(r[2]), "=r"(r[3]) : "r"(addr));
}
__device__ __forceinline__ void mma16816(float* c, const uint32_t* a, uint32_t b0, uint32_t b1) {
    asm volatile(
        "mma.sync.aligned.m16n8k16.row.col.f32.bf16.bf16.f32 "
        "{%0,%1,%2,%3}, {%4,%5,%6,%7}, {%8,%9}, {%0,%1,%2,%3};"
        : "+f"(c[0]), "+f"(c[1]), "+f"(c[2]), "+f"(c[3])
        : "r"(a[0]), "r"(a[1]), "r"(a[2]), "r"(a[3]), "r"(b0), "r"(b1));
}

__global__ __launch_bounds__(256) void gemm_mma(
    const __nv_bfloat16* __restrict__ Ahi, const __nv_bfloat16* __restrict__ Alo,
    const __nv_bfloat16* __restrict__ Bhi, const __nv_bfloat16* __restrict__ Blo,
    const float* __restrict__ bias, const float* __restrict__ res,
    float* __restrict__ out, int ldout)
{
    extern __shared__ char smem[];
    uint32_t sb = s2u(smem);
    int tid = threadIdx.x;
    int wid = tid >> 5, lane = tid & 31;
    int bm = blockIdx.y * BM, bn = blockIdx.x * BN;
    int wm = (wid & 3) * 32;
    int wn = (wid >> 2) * 64;

    const __nv_bfloat16* Asrc[3] = {Ahi, Ahi, Alo};
    const __nv_bfloat16* Bsrc[3] = {Bhi, Blo, Bhi};

    uint32_t offA[2][4], offB[4][4];
#pragma unroll
    for (int mt = 0; mt < 2; mt++)
#pragma unroll
        for (int ks = 0; ks < 4; ks++) {
            int row = wm + mt*16 + (lane & 7) + ((lane >> 3) & 1) * 8;
            int kc  = ks*2 + (lane >> 4);
            offA[mt][ks] = tile_off(row, kc);
        }
#pragma unroll
    for (int p = 0; p < 4; p++)
#pragma unroll
        for (int ks = 0; ks < 4; ks++) {
            int row = wn + p*16 + (lane & 7) + (lane >> 4) * 8;
            int kc  = ks*2 + ((lane >> 3) & 1);
            offB[p][ks] = tile_off(row, kc);
        }

    float acc[2][8][4];
#pragma unroll
    for (int mt = 0; mt < 2; mt++)
#pragma unroll
        for (int nt = 0; nt < 8; nt++)
#pragma unroll
            for (int q = 0; q < 4; q++) acc[mt][nt][q] = 0.0f;

    auto load_stage = [&](int slot, int iter) {
        int seg = iter >> 4;
        int k0  = (iter & 15) * BK;
        const __nv_bfloat16* A = Asrc[seg];
        const __nv_bfloat16* B = Bsrc[seg];
        uint32_t abase = sb + slot * STG_BYTES;
        uint32_t bbase = abase + BM * BK * 2;
#pragma unroll
        for (int j = 0; j < 4; j++) {
            int idx = tid + j * 256;
            int row = idx >> 3, c = idx & 7;
            cp16(abase + tile_off(row, c), A + (size_t)(bm + row) * DD + k0 + c * 8);
        }
#pragma unroll
        for (int j = 0; j < 4; j++) {
            int idx = tid + j * 256;
            int row = idx >> 3, c = idx & 7;
            cp16(bbase + tile_off(row, c), B + (size_t)(bn + row) * DD + k0 + c * 8);
        }
        cp_commit();
    };

#pragma unroll
    for (int s = 0; s < NSTG - 1; s++) load_stage(s, s);

    for (int i = 0; i < NIT; i++) {
        int slot = i % NSTG;
        int pend = NIT - 1 - i; if (pend > NSTG - 2) pend = NSTG - 2;
        cp_wait(pend);
        __syncthreads();

        uint32_t abase = sb + slot * STG_BYTES;
        uint32_t bbase = abase + BM * BK * 2;
#pragma unroll
        for (int ks = 0; ks < 4; ks++) {
            uint32_t a[2][4], b[4][4];
#pragma unroll
            for (int mt = 0; mt < 2; mt++) ldm4(a[mt], abase + offA[mt][ks]);
#pragma unroll
            for (int p = 0; p < 4; p++)    ldm4(b[p], bbase + offB[p][ks]);
#pragma unroll
            for (int mt = 0; mt < 2; mt++)
#pragma unroll
                for (int nt = 0; nt < 8; nt++)
                    mma16816(acc[mt][nt], a[mt], b[nt >> 1][(nt & 1) * 2], b[nt >> 1][(nt & 1) * 2 + 1]);
        }

        if (i + NSTG - 1 < NIT)
            load_stage((i + NSTG - 1) % NSTG, i + NSTG - 1);
    }

    int qr = lane >> 2, qc = (lane & 3) * 2;
#pragma unroll
    for (int mt = 0; mt < 2; mt++) {
#pragma unroll
        for (int nt = 0; nt < 8; nt++) {
            int col = bn + wn + nt * 8 + qc;
            float b0 = bias[col], b1 = bias[col + 1];
            int r0 = bm + wm + mt * 16 + qr;
            size_t g0 = (size_t)r0 * ldout + col;
            size_t g1 = g0 + (size_t)8 * ldout;
            float2 v0 = make_float2(acc[mt][nt][0] + b0, acc[mt][nt][1] + b1);
            float2 v1 = make_float2(acc[mt][nt][2] + b0, acc[mt][nt][3] + b1);
            if (res) {
                float2 x0 = *reinterpret_cast<const float2*>(res + g0);
                float2 x1 = *reinterpret_cast<const float2*>(res + g1);
                v0.x += x0.x; v0.y += x0.y;
                v1.x += x1.x; v1.y += x1.y;
            }
            *reinterpret_cast<float2*>(out + g0) = v0;
            *reinterpret_cast<float2*>(out + g1) = v1;
        }
    }
}

// ---------------- forward: norm keys, radix-4 FFT(k+iv), Kf & Kf*Vf ----------
// 2 tokens per 256-thread block; 128 threads per token, 2 butterflies/thread.
__global__ __launch_bounds__(256) void fwd_kernel() {
    __shared__ float2 sA[2][1024];
    __shared__ float2 sB[2][1024];
    __shared__ float red[8];
    int tid = threadIdx.x;
    int slot = tid >> 7;          // 0..1
    int ltid = tid & 127;
    int t = blockIdx.x * 2 + slot;

    const float* krow = g_kv + (size_t)t * 2048;
    const float* vrow = krow + 1024;
    float kx[8], vx[8];
#pragma unroll
    for (int m = 0; m < 8; m++) {
        kx[m] = krow[ltid + 128*m];
        vx[m] = vrow[ltid + 128*m];
    }

    float ss = 0.f;
#pragma unroll
    for (int m = 0; m < 8; m++) ss += kx[m]*kx[m];
#pragma unroll
    for (int o = 16; o; o >>= 1) ss += __shfl_xor_sync(0xffffffffu, ss, o);
    if ((tid & 31) == 0) red[tid >> 5] = ss;
    __syncthreads();
    float tot = red[slot*4] + red[slot*4+1] + red[slot*4+2] + red[slot*4+3];
    float scale = 1.0f / fmaxf(sqrtf(tot), 1e-12f);

#pragma unroll
    for (int m = 0; m < 8; m++)
        sA[slot][ltid + 128*m] = make_float2(kx[m]*scale, vx[m]);
    __syncthreads();

    // 5 radix-4 Stockham stages, N=1024, 2 butterflies per thread
    float2* src = sA[slot];
    float2* dst = sB[slot];
#pragma unroll
    for (int s = 0; s < 5; s++) {
        int Ns = 1 << (2*s);
#pragma unroll
        for (int q = 0; q < 2; q++) {
            int j = ltid + 128*q;
            int k = j & (Ns - 1);
            int twi = k << (8 - 2*s);          // 256*k/Ns
            float2 w1 = g_tw[twi];
            float2 w2 = g_tw[2*twi];
            float2 w3 = g_tw[3*twi];
            float2 a = src[j];
            float2 b = cmul(src[j + 256], w1);
            float2 c = cmul(src[j + 512], w2);
            float2 d = cmul(src[j + 768], w3);
            float2 t0 = make_float2(a.x + c.x, a.y + c.y);
            float2 t1 = make_float2(a.x - c.x, a.y - c.y);
            float2 t2 = make_float2(b.x + d.x, b.y + d.y);
            float2 t3 = make_float2(b.y - d.y, d.x - b.x);   // -i*(b-d)
            int idx = ((j >> (2*s)) << (2*s + 2)) + k;
            dst[idx]        = make_float2(t0.x + t2.x, t0.y + t2.y);
            dst[idx + Ns]   = make_float2(t1.x + t3.x, t1.y + t3.y);
            dst[idx + 2*Ns] = make_float2(t0.x - t2.x, t0.y - t2.y);
            dst[idx + 3*Ns] = make_float2(t1.x - t3.x, t1.y - t3.y);
        }
        __syncthreads();
        float2* tmp = src; src = dst; dst = tmp;
    }
    // result in src

#pragma unroll
    for (int e = 0; e < 4; e++) {
        int f = ltid + 128*e;            // 0..511
        float2 Zf = src[f];
        float2 Zn = src[(1024 - f) & 1023];
        float2 Kf = make_float2(0.5f*(Zf.x + Zn.x), 0.5f*(Zf.y - Zn.y));
        float2 Vf = make_float2(0.5f*(Zf.y + Zn.y), 0.5f*(Zn.x - Zf.x));
        size_t idx = (size_t)t * FF + f;
        g_kf[idx] = Kf;
        g_bf[idx] = cmul(Kf, Vf);
    }
    if (ltid == 0) {
        float2 Zf = src[512];
        float2 Kf = make_float2(Zf.x, 0.0f);
        float2 Vf = make_float2(Zf.y, 0.0f);
        size_t idx = (size_t)t * FF + 512;
        g_kf[idx] = Kf;
        g_bf[idx] = cmul(Kf, Vf);
    }
}

// ---------------- single-pass decoupled-lookback scan + unbind ----------------
__global__ __launch_bounds__(128) void scan_fused() {
    __shared__ int sflag;
    int tid = threadIdx.x;
    int bidx = blockIdx.x;
    int chain = bidx >> 6;          // 0..19  = b*5 + fg
    int c = bidx & 63;
    int b = chain / 5;
    int fg = chain % 5;
    int f = fg * 128 + tid;
    bool active = (f < FF);
    int tok0 = b * LL + c * CHTOK;

    // phase 1: chunk aggregate
    float2 sum = make_float2(0.f, 0.f);
    if (active) {
#pragma unroll 4
        for (int tt = 0; tt < CHTOK; tt++) {
            float2 v = g_bf[(size_t)(tok0 + tt) * FF + f];
            sum.x += v.x; sum.y += v.y;
        }
    }

    if (c == 0) {
        if (active) g_pre[(size_t)bidx * 128 + tid] = sum;
        __threadfence();
        __syncthreads();
        if (tid == 0) atomicExch(&g_flag[bidx], 2);
    } else {
        if (active) g_agg[(size_t)bidx * 128 + tid] = sum;
        __threadfence();
        __syncthreads();
        if (tid == 0) atomicExch(&g_flag[bidx], 1);
    }

    // lookback for exclusive prefix
    float2 run = make_float2(0.f, 0.f);
    if (c > 0) {
        int look = bidx - 1;
        while (true) {
            if (tid == 0) {
                int fl;
                do { fl = atomicAdd(&g_flag[look], 0); } while (fl == 0);
                sflag = fl;
            }
            __syncthreads();
            int fl = sflag;
            __threadfence();
            if (active) {
                float2 p = (fl == 2) ? g_pre[(size_t)look * 128 + tid]
                                     : g_agg[(size_t)look * 128 + tid];
                run.x += p.x; run.y += p.y;
            }
            __syncthreads();
            if (fl == 2) break;
            look--;
        }
        if (active)
            g_pre[(size_t)bidx * 128 + tid] = make_float2(run.x + sum.x, run.y + sum.y);
        __threadfence();
        __syncthreads();
        if (tid == 0) atomicExch(&g_flag[bidx], 2);
    }

    // phase 2: cumsum + unbind rf = Mf * conj(Kf)  (chunk re-read mostly L2-hit)
    if (active) {
        float2 acc = run;
        for (int tt = 0; tt < CHTOK; tt++) {
            size_t idx = (size_t)(tok0 + tt) * FF + f;
            float2 v = g_bf[idx];
            acc.x += v.x; acc.y += v.y;
            float2 kf = g_kf[idx];
            g_bf[idx] = make_float2(acc.x*kf.x + acc.y*kf.y, acc.y*kf.x - acc.x*kf.y);
        }
    }
}

// ---------------- inverse: 512-pt complex IFFT + LN + bf16 hi/lo split -------
// 4 tokens per 256-thread block; 64 threads per token, 2/4 butterflies per thread.
__global__ __launch_bounds__(256) void inv_kernel(const float* __restrict__ ln_g,
                                                  const float* __restrict__ ln_b) {
    __shared__ float2 sA[4][512];
    __shared__ float2 sB[4][512];
    __shared__ float2 rfny[4];
    __shared__ float red1[8];
    __shared__ float red2[8];
    int tid = threadIdx.x;
    int slot = tid >> 6;           // 0..3
    int ltid = tid & 63;
    int t = blockIdx.x * 4 + slot;
    int l = t % LL;

    const float2* rf = g_bf + (size_t)t * FF;
#pragma unroll
    for (int m = 0; m < 8; m++)
        sA[slot][ltid + 64*m] = rf[ltid + 64*m];
    if (ltid == 0) rfny[slot] = rf[512];
    __syncthreads();

    // Z[k] = 0.5*(X[k]+conj(X[512-k])) + 0.5*i*e^{+i*2pi*k/1024}*(X[k]-conj(X[512-k]))
#pragma unroll
    for (int m = 0; m < 8; m++) {
        int k = ltid + 64*m;
        float2 Xk = sA[slot][k];
        float2 Xm = (k == 0) ? rfny[slot] : sA[slot][512 - k];
        float2 sum = make_float2(Xk.x + Xm.x, Xk.y - Xm.y);
        float2 dif = make_float2(Xk.x - Xm.x, Xk.y + Xm.y);
        float2 wc = make_float2(g_tw[k].x, -g_tw[k].y);
        float2 t2 = cmul(wc, dif);
        sB[slot][k] = make_float2(0.5f*(sum.x - t2.y), 0.5f*(sum.y + t2.x));
    }
    __syncthreads();

    // inverse 512-pt FFT: 4 radix-4 stages (2 butterflies/thread) + radix-2 (4/thread)
    float2* src = sB[slot];
    float2* dst = sA[slot];
#pragma unroll
    for (int s = 0; s < 4; s++) {
        int Ns = 1 << (2*s);
#pragma unroll
        for (int q = 0; q < 2; q++) {
            int j = ltid + 64*q;
            int k = j & (Ns - 1);
            int twi = k << (8 - 2*s);
            float2 w1 = make_float2(g_tw[twi].x,   -g_tw[twi].y);
            float2 w2 = make_float2(g_tw[2*twi].x, -g_tw[2*twi].y);
            float2 w3 = make_float2(g_tw[3*twi].x, -g_tw[3*twi].y);
            float2 a = src[j];
            float2 b = cmul(src[j + 128], w1);
            float2 c = cmul(src[j + 256], w2);
            float2 d = cmul(src[j + 384], w3);
            float2 t0 = make_float2(a.x + c.x, a.y + c.y);
            float2 t1 = make_float2(a.x - c.x, a.y - c.y);
            float2 t2 = make_float2(b.x + d.x, b.y + d.y);
            float2 t3 = make_float2(d.y - b.y, b.x - d.x);   // +i*(b-d)
            int idx = ((j >> (2*s)) << (2*s + 2)) + k;
            dst[idx]        = make_float2(t0.x + t2.x, t0.y + t2.y);
            dst[idx + Ns]   = make_float2(t1.x + t3.x, t1.y + t3.y);
            dst[idx + 2*Ns] = make_float2(t0.x - t2.x, t0.y - t2.y);
            dst[idx + 3*Ns] = make_float2(t1.x - t3.x, t1.y - t3.y);
        }
        __syncthreads();
        float2* tmp = src; src = dst; dst = tmp;
    }
    // radix-2 final stage: 256 butterflies, 4 per thread
#pragma unroll
    for (int q = 0; q < 4; q++) {
        int j = ltid + 64*q;
        float2 w = make_float2(g_tw[2*j].x, -g_tw[2*j].y);
        float2 v0 = src[j];
        float2 v1 = src[j + 256];
        float2 tt = cmul(v1, w);
        dst[j]       = make_float2(v0.x + tt.x, v0.y + tt.y);
        dst[j + 256] = make_float2(v0.x - tt.x, v0.y - tt.y);
    }
    __syncthreads();
    float2* Z = dst;

    // thread covers z[2*ltid + 128*e], z[2*ltid+1 + 128*e] for e=0..3
    // -> x cols [256*e + 4*ltid .. +3]  (16 reals total)
    float s = (1.0f / 512.0f) * rsqrtf((float)(l + 1));
    float xv[4][4];
    float sum = 0.f, sq = 0.f;
#pragma unroll
    for (int e = 0; e < 4; e++) {
        float2 z0 = Z[2*ltid + 128*e];
        float2 z1 = Z[2*ltid + 1 + 128*e];
        xv[e][0] = z0.x * s; xv[e][1] = z0.y * s;
        xv[e][2] = z1.x * s; xv[e][3] = z1.y * s;
#pragma unroll
        for (int q = 0; q < 4; q++) { sum += xv[e][q]; sq += xv[e][q]*xv[e][q]; }
    }

#pragma unroll
    for (int o = 16; o; o >>= 1) {
        sum += __shfl_xor_sync(0xffffffffu, sum, o);
        sq  += __shfl_xor_sync(0xffffffffu, sq, o);
    }
    if ((tid & 31) == 0) { red1[tid >> 5] = sum; red2[tid >> 5] = sq; }
    __syncthreads();
    float tsum = red1[slot*2] + red1[slot*2+1];
    float tsq  = red2[slot*2] + red2[slot*2+1];
    float mu  = tsum * (1.0f / 1024.0f);
    float var = tsq * (1.0f / 1024.0f) - mu * mu;
    float inv = rsqrtf(var + 1e-5f);

    size_t rowoff = (size_t)t * DD;
#pragma unroll
    for (int e = 0; e < 4; e++) {
        int col = 256*e + 4*ltid;
        float4 gg = *reinterpret_cast<const float4*>(ln_g + col);
        float4 bb = *reinterpret_cast<const float4*>(ln_b + col);
        float r0 = (xv[e][0] - mu) * inv * gg.x + bb.x;
        float r1 = (xv[e][1] - mu) * inv * gg.y + bb.y;
        float r2 = (xv[e][2] - mu) * inv * gg.z + bb.z;
        float r3 = (xv[e][3] - mu) * inv * gg.w + bb.w;
        __nv_bfloat16 h0 = __float2bfloat16(r0);
        __nv_bfloat16 h1 = __float2bfloat16(r1);
        __nv_bfloat16 h2 = __float2bfloat16(r2);
        __nv_bfloat16 h3 = __float2bfloat16(r3);
        __nv_bfloat16 l0 = __float2bfloat16(r0 - __bfloat162float(h0));
        __nv_bfloat16 l1 = __float2bfloat16(r1 - __bfloat162float(h1));
        __nv_bfloat16 l2 = __float2bfloat16(r2 - __bfloat162float(h2));
        __nv_bfloat16 l3 = __float2bfloat16(r3 - __bfloat162float(h3));
        __nv_bfloat162* hp = reinterpret_cast<__nv_bfloat162*>(g_rhi + rowoff + col);
        __nv_bfloat162* lp = reinterpret_cast<__nv_bfloat162*>(g_rlo + rowoff + col);
        hp[0] = __halves2bfloat162(h0, h1); hp[1] = __halves2bfloat162(h2, h3);
        lp[0] = __halves2bfloat162(l0, l1); lp[1] = __halves2bfloat162(l2, l3);
    }
}

// ---------------- launch ------------------------------------------------------
extern "C" void kernel_launch(void* const* d_in, const int* in_sizes, int n_in,
                              void* d_out, int out_size) {
    const float* x    = (const float*)d_in[0];
    const float* Wk   = (const float*)d_in[1];
    const float* bk   = (const float*)d_in[2];
    const float* Wv   = (const float*)d_in[3];
    const float* bv   = (const float*)d_in[4];
    const float* ln_g = (const float*)d_in[5];
    const float* ln_b = (const float*)d_in[6];
    const float* Wo   = (const float*)d_in[7];
    const float* bo   = (const float*)d_in[8];
    float* out = (float*)d_out;

    void *p_kv;
    void *p_xhi, *p_xlo, *p_rhi, *p_rlo;
    void *p_wkvhi, *p_wkvlo, *p_wohi, *p_wolo, *p_bkv;
    cudaGetSymbolAddress(&p_kv,   g_kv);
    cudaGetSymbolAddress(&p_xhi,  g_xhi);
    cudaGetSymbolAddress(&p_xlo,  g_xlo);
    cudaGetSymbolAddress(&p_rhi,  g_rhi);
    cudaGetSymbolAddress(&p_rlo,  g_rlo);
    cudaGetSymbolAddress(&p_wkvhi, g_wkvhi);
    cudaGetSymbolAddress(&p_wkvlo, g_wkvlo);
    cudaGetSymbolAddress(&p_wohi, g_wohi);
    cudaGetSymbolAddress(&p_wolo, g_wolo);
    cudaGetSymbolAddress(&p_bkv,  g_bkv);

    cudaFuncSetAttribute(gemm_mma, cudaFuncAttributeMaxDynamicSharedMemorySize, GEMM_SMEM);

    setup_kernel<<<2, 1024>>>(bk, bv);

    int nx4 = MM * DD / 4;
    int nw4 = DD * DD / 4;
    split_conv<<<(nx4 + 255)/256, 256>>>(x, (__nv_bfloat16*)p_xhi, (__nv_bfloat16*)p_xlo, nx4);
    split_weights<<<(3*nw4 + 255)/256, 256>>>(Wk, Wv, Wo);

    // fused K+V projection: N = 2048
    dim3 kvgrid(2048 / BN, MM / BM);   // (16, 128)
    gemm_mma<<<kvgrid, 256, GEMM_SMEM>>>((__nv_bfloat16*)p_xhi, (__nv_bfloat16*)p_xlo,
                                         (__nv_bfloat16*)p_wkvhi, (__nv_bfloat16*)p_wkvlo,
                                         (const float*)p_bkv, nullptr, (float*)p_kv, 2048);

    fwd_kernel<<<MM/2, 256>>>();

    scan_fused<<<NBLK_SCAN, 128>>>();

    inv_kernel<<<MM/4, 256>>>(ln_g, ln_b);

    dim3 ogrid(DD / BN, MM / BM);      // (8, 128)
    gemm_mma<<<ogrid, 256, GEMM_SMEM>>>((__nv_bfloat16*)p_rhi, (__nv_bfloat16*)p_rlo,
                                        (__nv_bfloat16*)p_wohi, (__nv_bfloat16*)p_wolo,
                                        bo, x, out, DD);
}